// round 12
// baseline (speedup 1.0000x reference)
#include <cuda_runtime.h>
#include <cuda_bf16.h>
#include <cstdint>
#include <cstddef>

// ---------------------------------------------------------------------------
// ChannelAttention via Gram factorization (all heavy GEMMs on tensor cores):
//   G_b   = X_b^T X_b          (bf16x3 mma, ldmatrix.trans, split-K 8)
//   P1_b  = Wk @ G_b           (bf16x3 mma)
//   logit = softmax(SCALE * P1_h @ Wv_h^T)   (FFMA, tiny)
//   Wht_b = (attn_h @ Wq_h)^T                (FFMA, tiny, emits bf16 hi/lo)
//   Wt_b  = Wproj @ Wht_b^T                  (bf16x3 mma, emits bf16 hi/lo)
//   y     = X @ Wt_b^T + bproj               (bf16x3 mma)
// Round 12 (= round 11 resubmitted after infra failure): BK=32 with 2-stage
// cp.async — one barrier per 32-K tile so warp phases drift and LDSM bursts
// overlap MMA runs.
// ---------------------------------------------------------------------------

static constexpr int   kTok   = 8192;
static constexpr int   kC     = 512;
static constexpr int   kM     = 4 * kTok;       // 32768
static constexpr float kScale = 0.125f;
static constexpr int   kSplitK = 8;             // gram split-K
static constexpr int   kKS     = kTok / kSplitK;  // 1024 tokens per split

// Scratch (device globals; all read locations rewritten each launch)
__device__ __nv_bfloat16 g_xh [(size_t)kM * kC];
__device__ __nv_bfloat16 g_xl [(size_t)kM * kC];
__device__ float g_gpart[(size_t)kSplitK * 4 * kC * kC];
__device__ __nv_bfloat16 g_Gh [(size_t)4 * kC * kC];
__device__ __nv_bfloat16 g_Gl [(size_t)4 * kC * kC];
__device__ float g_P1   [(size_t)4 * kC * kC];
__device__ float g_attn [(size_t)32 * 64 * 64];
__device__ __nv_bfloat16 g_whth[(size_t)4 * kC * kC];
__device__ __nv_bfloat16 g_whtl[(size_t)4 * kC * kC];
__device__ __nv_bfloat16 g_wth[(size_t)4 * kC * kC];
__device__ __nv_bfloat16 g_wtl[(size_t)4 * kC * kC];
__device__ __nv_bfloat16 g_wkh[(size_t)kC * kC];
__device__ __nv_bfloat16 g_wkl[(size_t)kC * kC];
__device__ __nv_bfloat16 g_wph[(size_t)kC * kC];
__device__ __nv_bfloat16 g_wpl[(size_t)kC * kC];

// ---------------------------------------------------------------------------
// primitives
// ---------------------------------------------------------------------------
__device__ __forceinline__ void ldsm_x4(uint32_t addr, uint32_t* r)
{
    asm volatile("ldmatrix.sync.aligned.m8n8.x4.shared.b16 {%0,%1,%2,%3}, [%4];\n"
                 : "=r"(r[0]), "=r"(r[1]), "=r"(r[2]), "=r"(r[3]) : "r"(addr));
}
__device__ __forceinline__ void ldsm_x4_t(uint32_t addr, uint32_t* r)
{
    asm volatile("ldmatrix.sync.aligned.m8n8.x4.trans.shared.b16 {%0,%1,%2,%3}, [%4];\n"
                 : "=r"(r[0]), "=r"(r[1]), "=r"(r[2]), "=r"(r[3]) : "r"(addr));
}
__device__ __forceinline__ void mma16816(float* c, const uint32_t* a,
                                         uint32_t b0, uint32_t b1)
{
    asm volatile(
        "mma.sync.aligned.m16n8k16.row.col.f32.bf16.bf16.f32 "
        "{%0,%1,%2,%3}, {%4,%5,%6,%7}, {%8,%9}, {%0,%1,%2,%3};\n"
        : "+f"(c[0]), "+f"(c[1]), "+f"(c[2]), "+f"(c[3])
        : "r"(a[0]), "r"(a[1]), "r"(a[2]), "r"(a[3]), "r"(b0), "r"(b1));
}
__device__ __forceinline__ void cp16(uint32_t dst, const void* src)
{
    asm volatile("cp.async.cg.shared.global [%0], [%1], 16;\n" :: "r"(dst), "l"(src));
}
__device__ __forceinline__ void cp_commit()
{
    asm volatile("cp.async.commit_group;\n");
}
template <int N> __device__ __forceinline__ void cp_wait()
{
    asm volatile("cp.async.wait_group %0;\n" :: "n"(N));
}
__device__ __forceinline__ uint32_t pack_hi2(float a, float b)
{
    __nv_bfloat162 p;
    p.x = __float2bfloat16_rn(a);
    p.y = __float2bfloat16_rn(b);
    return *reinterpret_cast<uint32_t*>(&p);
}
__device__ __forceinline__ uint32_t pack_lo2(float a, float b, uint32_t hi)
{
    __nv_bfloat162 h = *reinterpret_cast<__nv_bfloat162*>(&hi);
    __nv_bfloat162 p;
    p.x = __float2bfloat16_rn(a - __bfloat162float(h.x));
    p.y = __float2bfloat16_rn(b - __bfloat162float(h.y));
    return *reinterpret_cast<uint32_t*>(&p);
}

// ---------------------------------------------------------------------------
// fp32 -> (hi, lo) bf16 split
// ---------------------------------------------------------------------------
__global__ __launch_bounds__(256) void split_f32(
    const float* __restrict__ src,
    __nv_bfloat16* __restrict__ hi, __nv_bfloat16* __restrict__ lo, int n4)
{
    int i = blockIdx.x * blockDim.x + threadIdx.x;
    if (i >= n4) return;
    float4 f = ((const float4*)src)[i];
    float a[4] = {f.x, f.y, f.z, f.w};
    __nv_bfloat16 h[4], l[4];
#pragma unroll
    for (int j = 0; j < 4; j++) {
        h[j] = __float2bfloat16_rn(a[j]);
        l[j] = __float2bfloat16_rn(a[j] - __bfloat162float(h[j]));
    }
    ((uint2*)hi)[i] = *(uint2*)h;
    ((uint2*)lo)[i] = *(uint2*)l;
}

// ---------------------------------------------------------------------------
// Gram partials (bf16x3, ldmatrix.trans), split-K 8, BK=32, 2-stage.
// 128 threads, 4 warps of 64x64. CTA tile 128x128 (upper-tri block pairs).
// Stage: Ah | Al | Bh | Bl, each 32 rows x 136 bf16 = 8704 B -> 34816 B.
// ---------------------------------------------------------------------------
static constexpr int kGramArr   = 32 * 136 * 2;       // 8704 B
static constexpr int kGramStage = 4 * kGramArr;       // 34816 B
static constexpr int kGramSmem  = 2 * kGramStage;     // 69632 B

__global__ __launch_bounds__(128, 2) void gemm_gram(
    const __nv_bfloat16* __restrict__ Xhi,
    const __nv_bfloat16* __restrict__ Xlo,
    float* __restrict__ part)
{
    extern __shared__ __align__(16) char smem[];
    const uint32_t sbase = (uint32_t)__cvta_generic_to_shared(smem);

    int p = blockIdx.x, mb = 0;
    while (p >= 4 - mb) { p -= 4 - mb; mb++; }
    const int m0 = mb * 128, n0 = (mb + p) * 128;
    const int bz = blockIdx.y;           // b*kSplitK + s
    const int b = bz >> 3, s = bz & 7;
    const size_t tokBase = (size_t)b * kTok + (size_t)s * kKS;

    const int tid = threadIdx.x, wid = tid >> 5, lane = tid & 31;
    const int wm = (wid >> 1) * 64, wn = (wid & 1) * 64;

    // loader: 32 rows x 16 chunks(8 bf16) per array; 128 thr -> 16 cp16 each
    const int lr0 = tid >> 3;              // rows lr0, lr0+16
    const int ch0 = (tid & 7) * 16;        // chunk cols ch0, ch0+8

    auto issue = [&](int kt) {
        const uint32_t stg = sbase + (uint32_t)(kt & 1) * kGramStage;
#pragma unroll
        for (int rh = 0; rh < 2; rh++) {
            const int row = lr0 + rh * 16;
            const size_t ro = (tokBase + (size_t)kt * 32 + row) * kC;
#pragma unroll
            for (int cg = 0; cg < 2; cg++) {
                const int ch = ch0 + cg * 8;
                const uint32_t d = (uint32_t)(row * 136 + ch) * 2;
                cp16(stg +                  d, Xhi + ro + m0 + ch);
                cp16(stg +     kGramArr   + d, Xlo + ro + m0 + ch);
                cp16(stg + 2 * kGramArr   + d, Xhi + ro + n0 + ch);
                cp16(stg + 3 * kGramArr   + d, Xlo + ro + n0 + ch);
            }
        }
        cp_commit();
    };

    // trans fragment lane mapping
    const int kA = (lane & 7) + ((lane >> 4) & 1) * 8;
    const int mA = ((lane >> 3) & 1) * 8;
    const int kB = (lane & 7) + ((lane >> 3) & 1) * 8;
    const int nB = ((lane >> 4) & 1) * 8;

    float acc[4][8][4];
#pragma unroll
    for (int mt = 0; mt < 4; mt++)
#pragma unroll
        for (int nt = 0; nt < 8; nt++)
#pragma unroll
            for (int i = 0; i < 4; i++) acc[mt][nt][i] = 0.f;

    const int NK = kKS / 32;   // 32
    issue(0);

#pragma unroll 1
    for (int kt = 0; kt < NK; kt++) {
        cp_wait<0>();
        __syncthreads();
        if (kt + 1 < NK) issue(kt + 1);

        const uint32_t stg = sbase + (uint32_t)(kt & 1) * kGramStage;
#pragma unroll
        for (int kk = 0; kk < 2; kk++) {
            uint32_t ahi[4][4], alo[4][4];
#pragma unroll
            for (int mt = 0; mt < 4; mt++) {
                const uint32_t co =
                    (uint32_t)((kk * 16 + kA) * 136 + wm + mt * 16 + mA) * 2;
                ldsm_x4_t(stg +            co, ahi[mt]);
                ldsm_x4_t(stg + kGramArr + co, alo[mt]);
            }
#pragma unroll
            for (int ng = 0; ng < 4; ng++) {
                uint32_t bh[4], bl[4];
                const uint32_t co =
                    (uint32_t)((kk * 16 + kB) * 136 + wn + ng * 16 + nB) * 2;
                ldsm_x4_t(stg + 2 * kGramArr + co, bh);
                ldsm_x4_t(stg + 3 * kGramArr + co, bl);
#pragma unroll
                for (int mt = 0; mt < 4; mt++) {
#pragma unroll
                    for (int j = 0; j < 2; j++) {
                        float* c = acc[mt][ng * 2 + j];
                        mma16816(c, ahi[mt], bh[2 * j], bh[2 * j + 1]);
                        mma16816(c, ahi[mt], bl[2 * j], bl[2 * j + 1]);
                        mma16816(c, alo[mt], bh[2 * j], bh[2 * j + 1]);
                    }
                }
            }
        }
    }

    const int g = lane >> 2, tg = lane & 3;
    float* P = part + (size_t)(s * 4 + b) * kC * kC;
#pragma unroll
    for (int mt = 0; mt < 4; mt++) {
#pragma unroll
        for (int nt = 0; nt < 8; nt++) {
            const int r   = m0 + wm + mt * 16 + g;
            const int col = n0 + wn + nt * 8 + tg * 2;
            *(float2*)(P + (size_t)r * kC + col) =
                make_float2(acc[mt][nt][0], acc[mt][nt][1]);
            *(float2*)(P + (size_t)(r + 8) * kC + col) =
                make_float2(acc[mt][nt][2], acc[mt][nt][3]);
        }
    }
}

// ---------------------------------------------------------------------------
// Reduce split-K partials with symmetric mirroring -> G as bf16 hi/lo.
// ---------------------------------------------------------------------------
__global__ __launch_bounds__(256) void reduce_g(
    const float* __restrict__ part,
    __nv_bfloat16* __restrict__ Gh, __nv_bfloat16* __restrict__ Gl)
{
    const int i = blockIdx.x * 256 + threadIdx.x;
    const int b = i >> 18;
    const int r = (i >> 9) & 511;
    const int c = i & 511;
    const size_t src = ((r >> 7) <= (c >> 7))
        ? ((size_t)r * kC + c) : ((size_t)c * kC + r);
    float sum = 0.f;
#pragma unroll
    for (int s = 0; s < kSplitK; s++)
        sum += part[(size_t)(s * 4 + b) * kC * kC + src];
    const size_t o = (size_t)b * kC * kC + (size_t)r * kC + c;
    __nv_bfloat16 h = __float2bfloat16_rn(sum);
    Gh[o] = h;
    Gl[o] = __float2bfloat16_rn(sum - __bfloat162float(h));
}

// ---------------------------------------------------------------------------
// bf16x3 tensor GEMM: C = A @ B^T, CTA 128x128 (4 warps of 64x64), K=512,
// batched over z, BK=32, 2-stage. outF -> fp32; else bf16 hi/lo out.
// Stage: Ah|Al|Bh|Bl each 128 rows x 40 bf16 (80B rows) = 10240 B -> 40960 B.
// ---------------------------------------------------------------------------
static constexpr int kYArr   = 128 * 40 * 2;   // 10240 B
static constexpr int kYStage = 4 * kYArr;      // 40960 B
static constexpr int kYSmem  = 2 * kYStage;    // 81920 B

__global__ __launch_bounds__(128, 2) void gemm_tcz(
    const __nv_bfloat16* __restrict__ Ahi, const __nv_bfloat16* __restrict__ Alo,
    size_t strideA,
    const __nv_bfloat16* __restrict__ Bhi, const __nv_bfloat16* __restrict__ Blo,
    size_t strideB,
    const float* __restrict__ bias,
    float* __restrict__ outF,
    __nv_bfloat16* __restrict__ outH, __nv_bfloat16* __restrict__ outL,
    int ldc, size_t strideC)
{
    extern __shared__ __align__(16) char smem[];
    const uint32_t sbase = (uint32_t)__cvta_generic_to_shared(smem);

    const int tid = threadIdx.x, wid = tid >> 5, lane = tid & 31;
    const int n0 = blockIdx.x * 128;
    const int m0 = blockIdx.y * 128;
    const int z  = blockIdx.z;
    const int wm = (wid >> 1) * 64, wn = (wid & 1) * 64;

    const __nv_bfloat16* Ah = Ahi + strideA * z + (size_t)m0 * kC;
    const __nv_bfloat16* Al = Alo + strideA * z + (size_t)m0 * kC;
    const __nv_bfloat16* Bh = Bhi + strideB * z + (size_t)n0 * kC;
    const __nv_bfloat16* Bl = Blo + strideB * z + (size_t)n0 * kC;

    // loader: 128 rows x 4 chunks(8 bf16) per array; 128 thr -> 16 cp16 each
    const int lr0 = tid >> 1;           // rows lr0, lr0+64
    const int lk0 = (tid & 1) * 8;      // k chunks lk0, lk0+16

    auto issue = [&](int kt) {
        const uint32_t stg = sbase + (uint32_t)(kt & 1) * kYStage;
#pragma unroll
        for (int rh = 0; rh < 2; rh++) {
            const int row = lr0 + rh * 64;
#pragma unroll
            for (int kg = 0; kg < 2; kg++) {
                const int ko = lk0 + kg * 16;
                const uint32_t d = (uint32_t)(row * 40 + ko) * 2;
                const size_t ro = (size_t)row * kC + kt * 32 + ko;
                cp16(stg +              d, Ah + ro);
                cp16(stg +     kYArr  + d, Al + ro);
                cp16(stg + 2 * kYArr  + d, Bh + ro);
                cp16(stg + 3 * kYArr  + d, Bl + ro);
            }
        }
        cp_commit();
    };

    const int aRow = lane & 15;
    const int aKof = (lane >> 4) * 8;
    const int bRow = (lane & 7) + ((lane >> 4) & 1) * 8;
    const int bKof = ((lane >> 3) & 1) * 8;

    float acc[4][8][4];
#pragma unroll
    for (int mt = 0; mt < 4; mt++)
#pragma unroll
        for (int nt = 0; nt < 8; nt++)
#pragma unroll
            for (int i = 0; i < 4; i++) acc[mt][nt][i] = 0.f;

    const int NK = kC / 32;   // 16
    issue(0);

#pragma unroll 1
    for (int kt = 0; kt < NK; kt++) {
        cp_wait<0>();
        __syncthreads();
        if (kt + 1 < NK) issue(kt + 1);

        const uint32_t stg = sbase + (uint32_t)(kt & 1) * kYStage;
#pragma unroll
        for (int kk = 0; kk < 2; kk++) {
            uint32_t ahi[4][4], alo[4][4];
#pragma unroll
            for (int mt = 0; mt < 4; mt++) {
                const uint32_t co =
                    (uint32_t)((wm + mt * 16 + aRow) * 40 + kk * 16 + aKof) * 2;
                ldsm_x4(stg +         co, ahi[mt]);
                ldsm_x4(stg + kYArr + co, alo[mt]);
            }
#pragma unroll
            for (int ng = 0; ng < 4; ng++) {
                uint32_t bh[4], bl[4];
                const uint32_t co =
                    (uint32_t)((wn + ng * 16 + bRow) * 40 + kk * 16 + bKof) * 2;
                ldsm_x4(stg + 2 * kYArr + co, bh);
                ldsm_x4(stg + 3 * kYArr + co, bl);
#pragma unroll
                for (int mt = 0; mt < 4; mt++) {
#pragma unroll
                    for (int j = 0; j < 2; j++) {
                        float* c = acc[mt][ng * 2 + j];
                        mma16816(c, ahi[mt], bh[2 * j], bh[2 * j + 1]);
                        mma16816(c, ahi[mt], bl[2 * j], bl[2 * j + 1]);
                        mma16816(c, alo[mt], bh[2 * j], bh[2 * j + 1]);
                    }
                }
            }
        }
    }

    const int g = lane >> 2, tg = lane & 3;
#pragma unroll
    for (int mt = 0; mt < 4; mt++) {
#pragma unroll
        for (int nt = 0; nt < 8; nt++) {
            const int r   = m0 + wm + mt * 16 + g;
            const int col = n0 + wn + nt * 8 + tg * 2;
            float v0 = acc[mt][nt][0], v1 = acc[mt][nt][1];
            float v2 = acc[mt][nt][2], v3 = acc[mt][nt][3];
            if (bias) {
                v0 += bias[col]; v1 += bias[col + 1];
                v2 += bias[col]; v3 += bias[col + 1];
            }
            const size_t o0 = strideC * z + (size_t)r * ldc + col;
            const size_t o1 = strideC * z + (size_t)(r + 8) * ldc + col;
            if (outF) {
                *(float2*)(outF + o0) = make_float2(v0, v1);
                *(float2*)(outF + o1) = make_float2(v2, v3);
            } else {
                uint32_t h0 = pack_hi2(v0, v1), h1 = pack_hi2(v2, v3);
                *(uint32_t*)(outH + o0) = h0;
                *(uint32_t*)(outH + o1) = h1;
                *(uint32_t*)(outL + o0) = pack_lo2(v0, v1, h0);
                *(uint32_t*)(outL + o1) = pack_lo2(v2, v3, h1);
            }
        }
    }
}

// ---------------------------------------------------------------------------
// logits_h = SCALE * P1_h @ Wv_h^T (64x64, K=512), row softmax -> attn.
// ---------------------------------------------------------------------------
__global__ __launch_bounds__(256) void logits_softmax(
    const float* __restrict__ P1, const float* __restrict__ Wqkv,
    float* __restrict__ attn)
{
    const int h = blockIdx.x, b = blockIdx.y;
    const float* p1 = P1 + (size_t)b * kC * kC + (size_t)(h * 64) * kC;
    const float* wv = Wqkv + (size_t)(1024 + h * 64) * kC;

    __shared__ float ps[16][68];
    __shared__ float vs[16][68];
    __shared__ float ls[64][68];

    const int tid = threadIdx.x;
    const int ty = tid >> 4, tx = tid & 15;
    const int lr = tid >> 2, lc = (tid & 3) * 4;

    float acc[4][4];
#pragma unroll
    for (int i = 0; i < 4; i++)
#pragma unroll
        for (int j = 0; j < 4; j++) acc[i][j] = 0.f;

    for (int c0 = 0; c0 < kC; c0 += 16) {
        float4 pv = *(const float4*)(p1 + (size_t)lr * kC + c0 + lc);
        float4 vv = *(const float4*)(wv + (size_t)lr * kC + c0 + lc);
        __syncthreads();
        ps[lc+0][lr]=pv.x; ps[lc+1][lr]=pv.y; ps[lc+2][lr]=pv.z; ps[lc+3][lr]=pv.w;
        vs[lc+0][lr]=vv.x; vs[lc+1][lr]=vv.y; vs[lc+2][lr]=vv.z; vs[lc+3][lr]=vv.w;
        __syncthreads();
#pragma unroll
        for (int cc = 0; cc < 16; cc++) {
            float a[4], v[4];
#pragma unroll
            for (int i = 0; i < 4; i++) a[i] = ps[cc][ty * 4 + i];
#pragma unroll
            for (int j = 0; j < 4; j++) v[j] = vs[cc][tx * 4 + j];
#pragma unroll
            for (int i = 0; i < 4; i++)
#pragma unroll
                for (int j = 0; j < 4; j++)
                    acc[i][j] += a[i] * v[j];
        }
    }

    __syncthreads();
#pragma unroll
    for (int i = 0; i < 4; i++)
#pragma unroll
        for (int j = 0; j < 4; j++)
            ls[ty * 4 + i][tx * 4 + j] = acc[i][j];
    __syncthreads();

    const int warp = tid >> 5, lane = tid & 31;
    float* arow_base = attn + (size_t)(b * 8 + h) * 4096;
    for (int r = 0; r < 8; r++) {
        const int d = warp * 8 + r;
        float v1 = kScale * ls[d][lane];
        float v2 = kScale * ls[d][lane + 32];
        float m = fmaxf(v1, v2);
#pragma unroll
        for (int s = 16; s > 0; s >>= 1)
            m = fmaxf(m, __shfl_xor_sync(0xffffffffu, m, s));
        float e1 = expf(v1 - m), e2 = expf(v2 - m);
        float sm = e1 + e2;
#pragma unroll
        for (int s = 16; s > 0; s >>= 1)
            sm += __shfl_xor_sync(0xffffffffu, sm, s);
        float inv = 1.f / sm;
        arow_base[d * 64 + lane]      = e1 * inv;
        arow_base[d * 64 + lane + 32] = e2 * inv;
    }
}

// ---------------------------------------------------------------------------
// Wht_b[c][h*64+d] = sum_e attn_h[d,e] * Wq[h*64+e][c] -> bf16 hi/lo.
// ---------------------------------------------------------------------------
static constexpr int kWhatSmem = (64 * 68 + 64 * 132) * 4;

__global__ __launch_bounds__(256) void what_t(
    const float* __restrict__ attn, const float* __restrict__ Wqkv,
    __nv_bfloat16* __restrict__ whth, __nv_bfloat16* __restrict__ whtl)
{
    extern __shared__ __align__(16) float ws[];
    float (*at)[68]  = (float(*)[68])ws;
    float (*wq)[132] = (float(*)[132])(ws + 64 * 68);

    const int h = blockIdx.x, b = blockIdx.y;
    const float* ag = attn + (size_t)(b * 8 + h) * 4096;
    const float* Wq = Wqkv + (size_t)(h * 64) * kC;
    const size_t obase = (size_t)b * kC * kC;

    const int tid = threadIdx.x;
    for (int i = tid; i < 4096; i += 256)
        at[i >> 6][i & 63] = ag[i];

    const int dG = (tid & 15) * 4;
    const int cB = tid >> 4;

    for (int cb = 0; cb < 4; cb++) {
        __syncthreads();
        for (int i = 0; i < 8; i++) {
            const int f4 = tid + i * 256;
            const int e  = f4 >> 5;
            const int cq = (f4 & 31) * 4;
            *(float4*)&wq[e][cq] =
                *(const float4*)(Wq + (size_t)e * kC + cb * 128 + cq);
        }
        __syncthreads();

        float o[8][4];
#pragma unroll
        for (int i = 0; i < 8; i++)
#pragma unroll
            for (int j = 0; j < 4; j++) o[i][j] = 0.f;

#pragma unroll 4
        for (int e = 0; e < 64; e++) {
            float a[4], w[8];
#pragma unroll
            for (int j = 0; j < 4; j++) a[j] = at[dG + j][e];
#pragma unroll
            for (int i = 0; i < 8; i++) w[i] = wq[e][cB * 8 + i];
#pragma unroll
            for (int i = 0; i < 8; i++)
#pragma unroll
                for (int j = 0; j < 4; j++)
                    o[i][j] += w[i] * a[j];
        }

#pragma unroll
        for (int i = 0; i < 8; i++) {
            const int c = cb * 128 + cB * 8 + i;
            const size_t oo = obase + (size_t)c * kC + h * 64 + dG;
            uint32_t h0 = pack_hi2(o[i][0], o[i][1]);
            uint32_t h1 = pack_hi2(o[i][2], o[i][3]);
            uint32_t l0 = pack_lo2(o[i][0], o[i][1], h0);
            uint32_t l1 = pack_lo2(o[i][2], o[i][3], h1);
            ((uint32_t*)(whth + oo))[0] = h0;
            ((uint32_t*)(whth + oo))[1] = h1;
            ((uint32_t*)(whtl + oo))[0] = l0;
            ((uint32_t*)(whtl + oo))[1] = l1;
        }
    }
}

// ---------------------------------------------------------------------------
extern "C" void kernel_launch(void* const* d_in, const int* in_sizes, int n_in,
                              void* d_out, int out_size)
{
    const float* x     = (const float*)d_in[0];
    const float* Wqkv  = (const float*)d_in[1];
    const float* Wproj = (const float*)d_in[2];
    const float* bproj = (const float*)d_in[3];
    float* out = (float*)d_out;

    __nv_bfloat16 *xh, *xl, *Gh, *Gl, *whth, *whtl, *wth, *wtl,
                  *wkh, *wkl, *wph, *wpl;
    float *gpart, *P1, *attn;
    cudaGetSymbolAddress((void**)&xh,    g_xh);
    cudaGetSymbolAddress((void**)&xl,    g_xl);
    cudaGetSymbolAddress((void**)&gpart, g_gpart);
    cudaGetSymbolAddress((void**)&Gh,    g_Gh);
    cudaGetSymbolAddress((void**)&Gl,    g_Gl);
    cudaGetSymbolAddress((void**)&P1,    g_P1);
    cudaGetSymbolAddress((void**)&attn,  g_attn);
    cudaGetSymbolAddress((void**)&whth,  g_whth);
    cudaGetSymbolAddress((void**)&whtl,  g_whtl);
    cudaGetSymbolAddress((void**)&wth,   g_wth);
    cudaGetSymbolAddress((void**)&wtl,   g_wtl);
    cudaGetSymbolAddress((void**)&wkh,   g_wkh);
    cudaGetSymbolAddress((void**)&wkl,   g_wkl);
    cudaGetSymbolAddress((void**)&wph,   g_wph);
    cudaGetSymbolAddress((void**)&wpl,   g_wpl);

    cudaFuncSetAttribute(gemm_gram,
        cudaFuncAttributeMaxDynamicSharedMemorySize, kGramSmem);
    cudaFuncSetAttribute(what_t,
        cudaFuncAttributeMaxDynamicSharedMemorySize, kWhatSmem);
    cudaFuncSetAttribute(gemm_tcz,
        cudaFuncAttributeMaxDynamicSharedMemorySize, kYSmem);

    const size_t cc = (size_t)kC * kC;

    // 1) splits: X, Wk (Wqkv rows 512..1024), Wproj
    split_f32<<<(kM * kC / 4 + 255) / 256, 256>>>(x, xh, xl, kM * kC / 4);
    split_f32<<<((int)cc / 4 + 255) / 256, 256>>>(Wqkv + cc, wkh, wkl, (int)cc / 4);
    split_f32<<<((int)cc / 4 + 255) / 256, 256>>>(Wproj, wph, wpl, (int)cc / 4);

    // 2) Gram partials (split-K 8, 128-thread CTAs, BK=32)
    gemm_gram<<<dim3(10, 4 * kSplitK), 128, kGramSmem>>>(xh, xl, gpart);

    // 3) reduce + mirror -> G (bf16 hi/lo)
    reduce_g<<<(4 * (int)cc) / 256, 256>>>(gpart, Gh, Gl);

    // 4) P1_b = Wk @ G_b  (G symmetric)  [tensor, fp32 out]
    gemm_tcz<<<dim3(4, 4, 4), 128, kYSmem>>>(
        wkh, wkl, 0, Gh, Gl, cc, nullptr, P1, nullptr, nullptr, kC, cc);

    // 5) logits + softmax -> attn
    logits_softmax<<<dim3(8, 4), 256>>>(P1, Wqkv, attn);

    // 6) Wht_b = (attn_h @ Wq_h)^T  -> bf16 hi/lo
    what_t<<<dim3(8, 4), 256, kWhatSmem>>>(attn, Wqkv, whth, whtl);

    // 7) Wt_b = Wproj @ Wht_b^T  [tensor, bf16 hi/lo out]
    gemm_tcz<<<dim3(4, 4, 4), 128, kYSmem>>>(
        wph, wpl, 0, whth, whtl, cc, nullptr, nullptr, wth, wtl, kC, cc);

    // 8) y = X @ Wt_b^T + bproj  [tensor]
    gemm_tcz<<<dim3(4, kTok / 128, 4), 128, kYSmem>>>(
        xh, xl, (size_t)kTok * kC, wth, wtl, cc, bproj,
        out, nullptr, nullptr, kC, (size_t)kTok * kC);
}

// round 13
// speedup vs baseline: 1.2913x; 1.2913x over previous
#include <cuda_runtime.h>
#include <cuda_bf16.h>
#include <cuda_fp16.h>
#include <cstdint>
#include <cstddef>

// ---------------------------------------------------------------------------
// ChannelAttention via Gram factorization.
//   G_b   = X_b^T X_b          (fp16x2 mma: A-split, B-single; split-K 8)
//   P1_b  = Wk @ G_b           (bf16x3 mma)
//   logit = softmax(SCALE * P1_h @ Wv_h^T)   (FFMA, tiny)
//   Wht_b = (attn_h @ Wq_h)^T                (FFMA, tiny, emits bf16 hi/lo)
//   Wt_b  = Wproj @ Wht_b^T                  (bf16x3 mma, emits fp16 single)
//   y     = X @ Wt_b^T + bproj               (fp16x2 mma)
// Round 13: revert to round-10 pipeline (BK=16, 3-stage, 64x64 warp tiles);
// big GEMMs switch bf16x3 -> fp16x2 (2 MMAs/logical-MMA, -33% tensor work).
// ---------------------------------------------------------------------------

static constexpr int   kTok   = 8192;
static constexpr int   kC     = 512;
static constexpr int   kM     = 4 * kTok;       // 32768
static constexpr float kScale = 0.125f;
static constexpr int   kSplitK = 8;             // gram split-K
static constexpr int   kKS     = kTok / kSplitK;  // 1024 tokens per split

// Scratch (device globals; all read locations rewritten each launch)
__device__ __half g_xh16[(size_t)kM * kC];
__device__ __half g_xl16[(size_t)kM * kC];
__device__ float g_gpart[(size_t)kSplitK * 4 * kC * kC];
__device__ __nv_bfloat16 g_Gh [(size_t)4 * kC * kC];
__device__ __nv_bfloat16 g_Gl [(size_t)4 * kC * kC];
__device__ float g_P1   [(size_t)4 * kC * kC];
__device__ float g_attn [(size_t)32 * 64 * 64];
__device__ __nv_bfloat16 g_whth[(size_t)4 * kC * kC];
__device__ __nv_bfloat16 g_whtl[(size_t)4 * kC * kC];
__device__ __half g_wt16[(size_t)4 * kC * kC];
__device__ __nv_bfloat16 g_wkh[(size_t)kC * kC];
__device__ __nv_bfloat16 g_wkl[(size_t)kC * kC];
__device__ __nv_bfloat16 g_wph[(size_t)kC * kC];
__device__ __nv_bfloat16 g_wpl[(size_t)kC * kC];

// ---------------------------------------------------------------------------
// primitives
// ---------------------------------------------------------------------------
__device__ __forceinline__ void ldsm_x4(uint32_t addr, uint32_t* r)
{
    asm volatile("ldmatrix.sync.aligned.m8n8.x4.shared.b16 {%0,%1,%2,%3}, [%4];\n"
                 : "=r"(r[0]), "=r"(r[1]), "=r"(r[2]), "=r"(r[3]) : "r"(addr));
}
__device__ __forceinline__ void ldsm_x4_t(uint32_t addr, uint32_t* r)
{
    asm volatile("ldmatrix.sync.aligned.m8n8.x4.trans.shared.b16 {%0,%1,%2,%3}, [%4];\n"
                 : "=r"(r[0]), "=r"(r[1]), "=r"(r[2]), "=r"(r[3]) : "r"(addr));
}
__device__ __forceinline__ void mma_bf16(float* c, const uint32_t* a,
                                         uint32_t b0, uint32_t b1)
{
    asm volatile(
        "mma.sync.aligned.m16n8k16.row.col.f32.bf16.bf16.f32 "
        "{%0,%1,%2,%3}, {%4,%5,%6,%7}, {%8,%9}, {%0,%1,%2,%3};\n"
        : "+f"(c[0]), "+f"(c[1]), "+f"(c[2]), "+f"(c[3])
        : "r"(a[0]), "r"(a[1]), "r"(a[2]), "r"(a[3]), "r"(b0), "r"(b1));
}
__device__ __forceinline__ void mma_f16(float* c, const uint32_t* a,
                                        uint32_t b0, uint32_t b1)
{
    asm volatile(
        "mma.sync.aligned.m16n8k16.row.col.f32.f16.f16.f32 "
        "{%0,%1,%2,%3}, {%4,%5,%6,%7}, {%8,%9}, {%0,%1,%2,%3};\n"
        : "+f"(c[0]), "+f"(c[1]), "+f"(c[2]), "+f"(c[3])
        : "r"(a[0]), "r"(a[1]), "r"(a[2]), "r"(a[3]), "r"(b0), "r"(b1));
}
__device__ __forceinline__ void cp16(uint32_t dst, const void* src)
{
    asm volatile("cp.async.cg.shared.global [%0], [%1], 16;\n" :: "r"(dst), "l"(src));
}
__device__ __forceinline__ void cp_commit()
{
    asm volatile("cp.async.commit_group;\n");
}
template <int N> __device__ __forceinline__ void cp_wait()
{
    asm volatile("cp.async.wait_group %0;\n" :: "n"(N));
}
__device__ __forceinline__ uint32_t pack_h2(float a, float b)
{
    __half2 p;
    p.x = __float2half_rn(a);
    p.y = __float2half_rn(b);
    return *reinterpret_cast<uint32_t*>(&p);
}

// ---------------------------------------------------------------------------
// fp32 -> (hi, lo) bf16 split
// ---------------------------------------------------------------------------
__global__ __launch_bounds__(256) void split_f32(
    const float* __restrict__ src,
    __nv_bfloat16* __restrict__ hi, __nv_bfloat16* __restrict__ lo, int n4)
{
    int i = blockIdx.x * blockDim.x + threadIdx.x;
    if (i >= n4) return;
    float4 f = ((const float4*)src)[i];
    float a[4] = {f.x, f.y, f.z, f.w};
    __nv_bfloat16 h[4], l[4];
#pragma unroll
    for (int j = 0; j < 4; j++) {
        h[j] = __float2bfloat16_rn(a[j]);
        l[j] = __float2bfloat16_rn(a[j] - __bfloat162float(h[j]));
    }
    ((uint2*)hi)[i] = *(uint2*)h;
    ((uint2*)lo)[i] = *(uint2*)l;
}

// fp32 -> (hi, lo) fp16 split
__global__ __launch_bounds__(256) void split_f16(
    const float* __restrict__ src,
    __half* __restrict__ hi, __half* __restrict__ lo, int n4)
{
    int i = blockIdx.x * blockDim.x + threadIdx.x;
    if (i >= n4) return;
    float4 f = ((const float4*)src)[i];
    float a[4] = {f.x, f.y, f.z, f.w};
    __half h[4], l[4];
#pragma unroll
    for (int j = 0; j < 4; j++) {
        h[j] = __float2half_rn(a[j]);
        l[j] = __float2half_rn(a[j] - __half2float(h[j]));
    }
    ((uint2*)hi)[i] = *(uint2*)h;
    ((uint2*)lo)[i] = *(uint2*)l;
}

// ---------------------------------------------------------------------------
// Gram partials (fp16x2: A split hi/lo, B single hi), split-K 8, BK=16,
// 3-stage. 128 threads, 4 warps of 64x64, CTA 128x128 upper-tri pairs.
// Stage: Ah | Al | Bh, each 16 rows x 136 fp16 = 4352 B -> 13056 B.
// ---------------------------------------------------------------------------
static constexpr int kGArr      = 16 * 136 * 2;       // 4352 B
static constexpr int kGramStage = 3 * kGArr;          // 13056 B
static constexpr int kGramSmem  = 3 * kGramStage;     // 39168 B

__global__ __launch_bounds__(128, 2) void gemm_gram16(
    const __half* __restrict__ Xhi,
    const __half* __restrict__ Xlo,
    float* __restrict__ part)
{
    extern __shared__ __align__(16) char smem[];
    const uint32_t sbase = (uint32_t)__cvta_generic_to_shared(smem);

    int p = blockIdx.x, mb = 0;
    while (p >= 4 - mb) { p -= 4 - mb; mb++; }
    const int m0 = mb * 128, n0 = (mb + p) * 128;
    const int bz = blockIdx.y;           // b*kSplitK + s
    const int b = bz >> 3, s = bz & 7;
    const size_t tokBase = (size_t)b * kTok + (size_t)s * kKS;

    const int tid = threadIdx.x, wid = tid >> 5, lane = tid & 31;
    const int wm = (wid >> 1) * 64, wn = (wid & 1) * 64;

    // loader: 16 rows x 16 chunks(8 fp16) per array; 128 thr -> 2 chunks each
    const int lr0 = tid >> 3;              // row 0..15
    const int ch0 = (tid & 7) * 16;        // chunk cols ch0, ch0+8

    auto issue = [&](int kt) {
        const uint32_t stg = sbase + (uint32_t)(kt % 3) * kGramStage;
        const size_t ro = (tokBase + (size_t)kt * 16 + lr0) * kC;
#pragma unroll
        for (int cg = 0; cg < 2; cg++) {
            const int ch = ch0 + cg * 8;
            const uint32_t d = (uint32_t)(lr0 * 136 + ch) * 2;
            cp16(stg +             d, Xhi + ro + m0 + ch);
            cp16(stg +     kGArr + d, Xlo + ro + m0 + ch);
            cp16(stg + 2 * kGArr + d, Xhi + ro + n0 + ch);
        }
        cp_commit();
    };

    // trans fragment lane mapping
    const int kA = (lane & 7) + ((lane >> 4) & 1) * 8;
    const int mA = ((lane >> 3) & 1) * 8;
    const int kB = (lane & 7) + ((lane >> 3) & 1) * 8;
    const int nB = ((lane >> 4) & 1) * 8;

    float acc[4][8][4];
#pragma unroll
    for (int mt = 0; mt < 4; mt++)
#pragma unroll
        for (int nt = 0; nt < 8; nt++)
#pragma unroll
            for (int i = 0; i < 4; i++) acc[mt][nt][i] = 0.f;

    const int NK = kKS / 16;   // 64
    issue(0); issue(1);

#pragma unroll 1
    for (int kt = 0; kt < NK; kt++) {
        cp_wait<1>();
        __syncthreads();
        if (kt + 2 < NK) issue(kt + 2);
        else             cp_commit();

        const uint32_t stg = sbase + (uint32_t)(kt % 3) * kGramStage;
        uint32_t ahi[4][4], alo[4][4];
#pragma unroll
        for (int mt = 0; mt < 4; mt++) {
            const uint32_t co = (uint32_t)(kA * 136 + wm + mt * 16 + mA) * 2;
            ldsm_x4_t(stg +         co, ahi[mt]);
            ldsm_x4_t(stg + kGArr + co, alo[mt]);
        }
#pragma unroll
        for (int ng = 0; ng < 4; ng++) {
            uint32_t bh[4];
            const uint32_t co = (uint32_t)(kB * 136 + wn + ng * 16 + nB) * 2;
            ldsm_x4_t(stg + 2 * kGArr + co, bh);
#pragma unroll
            for (int mt = 0; mt < 4; mt++) {
#pragma unroll
                for (int j = 0; j < 2; j++) {
                    float* c = acc[mt][ng * 2 + j];
                    mma_f16(c, ahi[mt], bh[2 * j], bh[2 * j + 1]);
                    mma_f16(c, alo[mt], bh[2 * j], bh[2 * j + 1]);
                }
            }
        }
    }

    const int g = lane >> 2, tg = lane & 3;
    float* P = part + (size_t)(s * 4 + b) * kC * kC;
#pragma unroll
    for (int mt = 0; mt < 4; mt++) {
#pragma unroll
        for (int nt = 0; nt < 8; nt++) {
            const int r   = m0 + wm + mt * 16 + g;
            const int col = n0 + wn + nt * 8 + tg * 2;
            *(float2*)(P + (size_t)r * kC + col) =
                make_float2(acc[mt][nt][0], acc[mt][nt][1]);
            *(float2*)(P + (size_t)(r + 8) * kC + col) =
                make_float2(acc[mt][nt][2], acc[mt][nt][3]);
        }
    }
}

// ---------------------------------------------------------------------------
// Reduce split-K partials with symmetric mirroring -> G as bf16 hi/lo.
// ---------------------------------------------------------------------------
__global__ __launch_bounds__(256) void reduce_g(
    const float* __restrict__ part,
    __nv_bfloat16* __restrict__ Gh, __nv_bfloat16* __restrict__ Gl)
{
    const int i = blockIdx.x * 256 + threadIdx.x;
    const int b = i >> 18;
    const int r = (i >> 9) & 511;
    const int c = i & 511;
    const size_t src = ((r >> 7) <= (c >> 7))
        ? ((size_t)r * kC + c) : ((size_t)c * kC + r);
    float sum = 0.f;
#pragma unroll
    for (int s = 0; s < kSplitK; s++)
        sum += part[(size_t)(s * 4 + b) * kC * kC + src];
    const size_t o = (size_t)b * kC * kC + (size_t)r * kC + c;
    __nv_bfloat16 h = __float2bfloat16_rn(sum);
    Gh[o] = h;
    Gl[o] = __float2bfloat16_rn(sum - __bfloat162float(h));
}

// ---------------------------------------------------------------------------
// bf16x3 tensor GEMM (middle GEMMs): C = A @ B^T, CTA 128x128 (4 warps of
// 64x64), K=512, batched over z, BK=16, 3-stage.
// outF -> fp32 out (+bias), else out16 -> fp16 single out.
// Stage: Ah|Al|Bh|Bl each 128 rows x 24 bf16 = 6144 B -> 24576 B.
// ---------------------------------------------------------------------------
static constexpr int kYArr   = 128 * 24 * 2;   // 6144 B
static constexpr int kYStage = 4 * kYArr;      // 24576 B
static constexpr int kYSmem  = 3 * kYStage;    // 73728 B

__global__ __launch_bounds__(128, 2) void gemm_tcz(
    const __nv_bfloat16* __restrict__ Ahi, const __nv_bfloat16* __restrict__ Alo,
    size_t strideA,
    const __nv_bfloat16* __restrict__ Bhi, const __nv_bfloat16* __restrict__ Blo,
    size_t strideB,
    float* __restrict__ outF,
    __half* __restrict__ out16,
    int ldc, size_t strideC)
{
    extern __shared__ __align__(16) char smem[];
    const uint32_t sbase = (uint32_t)__cvta_generic_to_shared(smem);

    const int tid = threadIdx.x, wid = tid >> 5, lane = tid & 31;
    const int n0 = blockIdx.x * 128;
    const int m0 = blockIdx.y * 128;
    const int z  = blockIdx.z;
    const int wm = (wid >> 1) * 64, wn = (wid & 1) * 64;

    const __nv_bfloat16* Ah = Ahi + strideA * z + (size_t)m0 * kC;
    const __nv_bfloat16* Al = Alo + strideA * z + (size_t)m0 * kC;
    const __nv_bfloat16* Bh = Bhi + strideB * z + (size_t)n0 * kC;
    const __nv_bfloat16* Bl = Blo + strideB * z + (size_t)n0 * kC;

    const int lr0 = tid >> 1;           // rows lr0, lr0+64
    const int lk8 = (tid & 1) * 8;      // 0 or 8

    auto issue = [&](int kt) {
        const uint32_t stg = sbase + (uint32_t)(kt % 3) * kYStage;
#pragma unroll
        for (int half = 0; half < 2; half++) {
            const int row = lr0 + half * 64;
            const uint32_t d = (uint32_t)(row * 24 + lk8) * 2;
            const size_t ro = (size_t)row * kC + kt * 16 + lk8;
            cp16(stg +             d, Ah + ro);
            cp16(stg +     kYArr + d, Al + ro);
            cp16(stg + 2 * kYArr + d, Bh + ro);
            cp16(stg + 3 * kYArr + d, Bl + ro);
        }
        cp_commit();
    };

    const int aRow = lane & 15;
    const int aKof = (lane >> 4) * 8;
    const int bRow = (lane & 7) + ((lane >> 4) & 1) * 8;
    const int bKof = ((lane >> 3) & 1) * 8;

    float acc[4][8][4];
#pragma unroll
    for (int mt = 0; mt < 4; mt++)
#pragma unroll
        for (int nt = 0; nt < 8; nt++)
#pragma unroll
            for (int i = 0; i < 4; i++) acc[mt][nt][i] = 0.f;

    const int NK = kC / 16;   // 32
    issue(0); issue(1);

#pragma unroll 1
    for (int kt = 0; kt < NK; kt++) {
        cp_wait<1>();
        __syncthreads();
        if (kt + 2 < NK) issue(kt + 2);
        else             cp_commit();

        const uint32_t stg = sbase + (uint32_t)(kt % 3) * kYStage;
        uint32_t ahi[4][4], alo[4][4];
#pragma unroll
        for (int mt = 0; mt < 4; mt++) {
            const uint32_t co = (uint32_t)((wm + mt * 16 + aRow) * 24 + aKof) * 2;
            ldsm_x4(stg +         co, ahi[mt]);
            ldsm_x4(stg + kYArr + co, alo[mt]);
        }
#pragma unroll
        for (int ng = 0; ng < 4; ng++) {
            uint32_t bh[4], bl[4];
            const uint32_t co = (uint32_t)((wn + ng * 16 + bRow) * 24 + bKof) * 2;
            ldsm_x4(stg + 2 * kYArr + co, bh);
            ldsm_x4(stg + 3 * kYArr + co, bl);
#pragma unroll
            for (int mt = 0; mt < 4; mt++) {
#pragma unroll
                for (int j = 0; j < 2; j++) {
                    float* c = acc[mt][ng * 2 + j];
                    mma_bf16(c, ahi[mt], bh[2 * j], bh[2 * j + 1]);
                    mma_bf16(c, ahi[mt], bl[2 * j], bl[2 * j + 1]);
                    mma_bf16(c, alo[mt], bh[2 * j], bh[2 * j + 1]);
                }
            }
        }
    }

    const int g = lane >> 2, tg = lane & 3;
#pragma unroll
    for (int mt = 0; mt < 4; mt++) {
#pragma unroll
        for (int nt = 0; nt < 8; nt++) {
            const int r   = m0 + wm + mt * 16 + g;
            const int col = n0 + wn + nt * 8 + tg * 2;
            const float v0 = acc[mt][nt][0], v1 = acc[mt][nt][1];
            const float v2 = acc[mt][nt][2], v3 = acc[mt][nt][3];
            const size_t o0 = strideC * z + (size_t)r * ldc + col;
            const size_t o1 = strideC * z + (size_t)(r + 8) * ldc + col;
            if (outF) {
                *(float2*)(outF + o0) = make_float2(v0, v1);
                *(float2*)(outF + o1) = make_float2(v2, v3);
            } else {
                *(uint32_t*)(out16 + o0) = pack_h2(v0, v1);
                *(uint32_t*)(out16 + o1) = pack_h2(v2, v3);
            }
        }
    }
}

// ---------------------------------------------------------------------------
// fp16x2 tensor GEMM (y): C = A @ B^T + bias; A fp16 split (hi/lo), B fp16.
// CTA 128x128 (4 warps of 64x64), K=512, batched over z, BK=16, 3-stage.
// Stage: Ah|Al|Bh each 128 rows x 24 fp16 = 6144 B -> 18432 B.
// ---------------------------------------------------------------------------
static constexpr int kY2Stage = 3 * kYArr;      // 18432 B
static constexpr int kY2Smem  = 3 * kY2Stage;   // 55296 B

__global__ __launch_bounds__(128, 2) void gemm_y16(
    const __half* __restrict__ Ahi, const __half* __restrict__ Alo,
    const __half* __restrict__ Bh16,
    const float* __restrict__ bias, float* __restrict__ C)
{
    extern __shared__ __align__(16) char smem[];
    const uint32_t sbase = (uint32_t)__cvta_generic_to_shared(smem);

    const int tid = threadIdx.x, wid = tid >> 5, lane = tid & 31;
    const int n0 = blockIdx.x * 128;
    const int m0 = blockIdx.y * 128;
    const int z  = blockIdx.z;
    const int wm = (wid >> 1) * 64, wn = (wid & 1) * 64;

    const __half* Ah = Ahi + ((size_t)z * kTok + m0) * kC;
    const __half* Al = Alo + ((size_t)z * kTok + m0) * kC;
    const __half* Bh = Bh16 + (size_t)z * kC * kC + (size_t)n0 * kC;

    const int lr0 = tid >> 1;
    const int lk8 = (tid & 1) * 8;

    auto issue = [&](int kt) {
        const uint32_t stg = sbase + (uint32_t)(kt % 3) * kY2Stage;
#pragma unroll
        for (int half = 0; half < 2; half++) {
            const int row = lr0 + half * 64;
            const uint32_t d = (uint32_t)(row * 24 + lk8) * 2;
            const size_t ro = (size_t)row * kC + kt * 16 + lk8;
            cp16(stg +             d, Ah + ro);
            cp16(stg +     kYArr + d, Al + ro);
            cp16(stg + 2 * kYArr + d, Bh + ro);
        }
        cp_commit();
    };

    const int aRow = lane & 15;
    const int aKof = (lane >> 4) * 8;
    const int bRow = (lane & 7) + ((lane >> 4) & 1) * 8;
    const int bKof = ((lane >> 3) & 1) * 8;

    float acc[4][8][4];
#pragma unroll
    for (int mt = 0; mt < 4; mt++)
#pragma unroll
        for (int nt = 0; nt < 8; nt++)
#pragma unroll
            for (int i = 0; i < 4; i++) acc[mt][nt][i] = 0.f;

    const int NK = kC / 16;   // 32
    issue(0); issue(1);

#pragma unroll 1
    for (int kt = 0; kt < NK; kt++) {
        cp_wait<1>();
        __syncthreads();
        if (kt + 2 < NK) issue(kt + 2);
        else             cp_commit();

        const uint32_t stg = sbase + (uint32_t)(kt % 3) * kY2Stage;
        uint32_t ahi[4][4], alo[4][4];
#pragma unroll
        for (int mt = 0; mt < 4; mt++) {
            const uint32_t co = (uint32_t)((wm + mt * 16 + aRow) * 24 + aKof) * 2;
            ldsm_x4(stg +         co, ahi[mt]);
            ldsm_x4(stg + kYArr + co, alo[mt]);
        }
#pragma unroll
        for (int ng = 0; ng < 4; ng++) {
            uint32_t bh[4];
            const uint32_t co = (uint32_t)((wn + ng * 16 + bRow) * 24 + bKof) * 2;
            ldsm_x4(stg + 2 * kYArr + co, bh);
#pragma unroll
            for (int mt = 0; mt < 4; mt++) {
#pragma unroll
                for (int j = 0; j < 2; j++) {
                    float* c = acc[mt][ng * 2 + j];
                    mma_f16(c, ahi[mt], bh[2 * j], bh[2 * j + 1]);
                    mma_f16(c, alo[mt], bh[2 * j], bh[2 * j + 1]);
                }
            }
        }
    }

    const int g = lane >> 2, tg = lane & 3;
#pragma unroll
    for (int mt = 0; mt < 4; mt++) {
#pragma unroll
        for (int nt = 0; nt < 8; nt++) {
            const int r   = m0 + wm + mt * 16 + g;
            const int col = n0 + wn + nt * 8 + tg * 2;
            const float b0 = bias[col], b1 = bias[col + 1];
            float* crow = C + ((size_t)z * kTok + r) * kC + col;
            *(float2*)(crow) =
                make_float2(acc[mt][nt][0] + b0, acc[mt][nt][1] + b1);
            *(float2*)(crow + (size_t)8 * kC) =
                make_float2(acc[mt][nt][2] + b0, acc[mt][nt][3] + b1);
        }
    }
}

// ---------------------------------------------------------------------------
// logits_h = SCALE * P1_h @ Wv_h^T (64x64, K=512), row softmax -> attn.
// ---------------------------------------------------------------------------
__global__ __launch_bounds__(256) void logits_softmax(
    const float* __restrict__ P1, const float* __restrict__ Wqkv,
    float* __restrict__ attn)
{
    const int h = blockIdx.x, b = blockIdx.y;
    const float* p1 = P1 + (size_t)b * kC * kC + (size_t)(h * 64) * kC;
    const float* wv = Wqkv + (size_t)(1024 + h * 64) * kC;

    __shared__ float ps[16][68];
    __shared__ float vs[16][68];
    __shared__ float ls[64][68];

    const int tid = threadIdx.x;
    const int ty = tid >> 4, tx = tid & 15;
    const int lr = tid >> 2, lc = (tid & 3) * 4;

    float acc[4][4];
#pragma unroll
    for (int i = 0; i < 4; i++)
#pragma unroll
        for (int j = 0; j < 4; j++) acc[i][j] = 0.f;

    for (int c0 = 0; c0 < kC; c0 += 16) {
        float4 pv = *(const float4*)(p1 + (size_t)lr * kC + c0 + lc);
        float4 vv = *(const float4*)(wv + (size_t)lr * kC + c0 + lc);
        __syncthreads();
        ps[lc+0][lr]=pv.x; ps[lc+1][lr]=pv.y; ps[lc+2][lr]=pv.z; ps[lc+3][lr]=pv.w;
        vs[lc+0][lr]=vv.x; vs[lc+1][lr]=vv.y; vs[lc+2][lr]=vv.z; vs[lc+3][lr]=vv.w;
        __syncthreads();
#pragma unroll
        for (int cc = 0; cc < 16; cc++) {
            float a[4], v[4];
#pragma unroll
            for (int i = 0; i < 4; i++) a[i] = ps[cc][ty * 4 + i];
#pragma unroll
            for (int j = 0; j < 4; j++) v[j] = vs[cc][tx * 4 + j];
#pragma unroll
            for (int i = 0; i < 4; i++)
#pragma unroll
                for (int j = 0; j < 4; j++)
                    acc[i][j] += a[i] * v[j];
        }
    }

    __syncthreads();
#pragma unroll
    for (int i = 0; i < 4; i++)
#pragma unroll
        for (int j = 0; j < 4; j++)
            ls[ty * 4 + i][tx * 4 + j] = acc[i][j];
    __syncthreads();

    const int warp = tid >> 5, lane = tid & 31;
    float* arow_base = attn + (size_t)(b * 8 + h) * 4096;
    for (int r = 0; r < 8; r++) {
        const int d = warp * 8 + r;
        float v1 = kScale * ls[d][lane];
        float v2 = kScale * ls[d][lane + 32];
        float m = fmaxf(v1, v2);
#pragma unroll
        for (int s = 16; s > 0; s >>= 1)
            m = fmaxf(m, __shfl_xor_sync(0xffffffffu, m, s));
        float e1 = expf(v1 - m), e2 = expf(v2 - m);
        float sm = e1 + e2;
#pragma unroll
        for (int s = 16; s > 0; s >>= 1)
            sm += __shfl_xor_sync(0xffffffffu, sm, s);
        float inv = 1.f / sm;
        arow_base[d * 64 + lane]      = e1 * inv;
        arow_base[d * 64 + lane + 32] = e2 * inv;
    }
}

// ---------------------------------------------------------------------------
// Wht_b[c][h*64+d] = sum_e attn_h[d,e] * Wq[h*64+e][c] -> bf16 hi/lo.
// ---------------------------------------------------------------------------
static constexpr int kWhatSmem = (64 * 68 + 64 * 132) * 4;

__device__ __forceinline__ uint32_t pack_hi2b(float a, float b)
{
    __nv_bfloat162 p;
    p.x = __float2bfloat16_rn(a);
    p.y = __float2bfloat16_rn(b);
    return *reinterpret_cast<uint32_t*>(&p);
}
__device__ __forceinline__ uint32_t pack_lo2b(float a, float b, uint32_t hi)
{
    __nv_bfloat162 h = *reinterpret_cast<__nv_bfloat162*>(&hi);
    __nv_bfloat162 p;
    p.x = __float2bfloat16_rn(a - __bfloat162float(h.x));
    p.y = __float2bfloat16_rn(b - __bfloat162float(h.y));
    return *reinterpret_cast<uint32_t*>(&p);
}

__global__ __launch_bounds__(256) void what_t(
    const float* __restrict__ attn, const float* __restrict__ Wqkv,
    __nv_bfloat16* __restrict__ whth, __nv_bfloat16* __restrict__ whtl)
{
    extern __shared__ __align__(16) float ws[];
    float (*at)[68]  = (float(*)[68])ws;
    float (*wq)[132] = (float(*)[132])(ws + 64 * 68);

    const int h = blockIdx.x, b = blockIdx.y;
    const float* ag = attn + (size_t)(b * 8 + h) * 4096;
    const float* Wq = Wqkv + (size_t)(h * 64) * kC;
    const size_t obase = (size_t)b * kC * kC;

    const int tid = threadIdx.x;
    for (int i = tid; i < 4096; i += 256)
        at[i >> 6][i & 63] = ag[i];

    const int dG = (tid & 15) * 4;
    const int cB = tid >> 4;

    for (int cb = 0; cb < 4; cb++) {
        __syncthreads();
        for (int i = 0; i < 8; i++) {
            const int f4 = tid + i * 256;
            const int e  = f4 >> 5;
            const int cq = (f4 & 31) * 4;
            *(float4*)&wq[e][cq] =
                *(const float4*)(Wq + (size_t)e * kC + cb * 128 + cq);
        }
        __syncthreads();

        float o[8][4];
#pragma unroll
        for (int i = 0; i < 8; i++)
#pragma unroll
            for (int j = 0; j < 4; j++) o[i][j] = 0.f;

#pragma unroll 4
        for (int e = 0; e < 64; e++) {
            float a[4], w[8];
#pragma unroll
            for (int j = 0; j < 4; j++) a[j] = at[dG + j][e];
#pragma unroll
            for (int i = 0; i < 8; i++) w[i] = wq[e][cB * 8 + i];
#pragma unroll
            for (int i = 0; i < 8; i++)
#pragma unroll
                for (int j = 0; j < 4; j++)
                    o[i][j] += w[i] * a[j];
        }

#pragma unroll
        for (int i = 0; i < 8; i++) {
            const int c = cb * 128 + cB * 8 + i;
            const size_t oo = obase + (size_t)c * kC + h * 64 + dG;
            uint32_t h0 = pack_hi2b(o[i][0], o[i][1]);
            uint32_t h1 = pack_hi2b(o[i][2], o[i][3]);
            uint32_t l0 = pack_lo2b(o[i][0], o[i][1], h0);
            uint32_t l1 = pack_lo2b(o[i][2], o[i][3], h1);
            ((uint32_t*)(whth + oo))[0] = h0;
            ((uint32_t*)(whth + oo))[1] = h1;
            ((uint32_t*)(whtl + oo))[0] = l0;
            ((uint32_t*)(whtl + oo))[1] = l1;
        }
    }
}

// ---------------------------------------------------------------------------
extern "C" void kernel_launch(void* const* d_in, const int* in_sizes, int n_in,
                              void* d_out, int out_size)
{
    const float* x     = (const float*)d_in[0];
    const float* Wqkv  = (const float*)d_in[1];
    const float* Wproj = (const float*)d_in[2];
    const float* bproj = (const float*)d_in[3];
    float* out = (float*)d_out;

    __half *xh16, *xl16, *wt16;
    __nv_bfloat16 *Gh, *Gl, *whth, *whtl, *wkh, *wkl, *wph, *wpl;
    float *gpart, *P1, *attn;
    cudaGetSymbolAddress((void**)&xh16,  g_xh16);
    cudaGetSymbolAddress((void**)&xl16,  g_xl16);
    cudaGetSymbolAddress((void**)&gpart, g_gpart);
    cudaGetSymbolAddress((void**)&Gh,    g_Gh);
    cudaGetSymbolAddress((void**)&Gl,    g_Gl);
    cudaGetSymbolAddress((void**)&P1,    g_P1);
    cudaGetSymbolAddress((void**)&attn,  g_attn);
    cudaGetSymbolAddress((void**)&whth,  g_whth);
    cudaGetSymbolAddress((void**)&whtl,  g_whtl);
    cudaGetSymbolAddress((void**)&wt16,  g_wt16);
    cudaGetSymbolAddress((void**)&wkh,   g_wkh);
    cudaGetSymbolAddress((void**)&wkl,   g_wkl);
    cudaGetSymbolAddress((void**)&wph,   g_wph);
    cudaGetSymbolAddress((void**)&wpl,   g_wpl);

    cudaFuncSetAttribute(gemm_gram16,
        cudaFuncAttributeMaxDynamicSharedMemorySize, kGramSmem);
    cudaFuncSetAttribute(what_t,
        cudaFuncAttributeMaxDynamicSharedMemorySize, kWhatSmem);
    cudaFuncSetAttribute(gemm_tcz,
        cudaFuncAttributeMaxDynamicSharedMemorySize, kYSmem);
    cudaFuncSetAttribute(gemm_y16,
        cudaFuncAttributeMaxDynamicSharedMemorySize, kY2Smem);

    const size_t cc = (size_t)kC * kC;

    // 1) splits: X -> fp16 hi/lo; Wk, Wproj -> bf16 hi/lo
    split_f16<<<(kM * kC / 4 + 255) / 256, 256>>>(x, xh16, xl16, kM * kC / 4);
    split_f32<<<((int)cc / 4 + 255) / 256, 256>>>(Wqkv + cc, wkh, wkl, (int)cc / 4);
    split_f32<<<((int)cc / 4 + 255) / 256, 256>>>(Wproj, wph, wpl, (int)cc / 4);

    // 2) Gram partials (fp16x2, split-K 8)
    gemm_gram16<<<dim3(10, 4 * kSplitK), 128, kGramSmem>>>(xh16, xl16, gpart);

    // 3) reduce + mirror -> G (bf16 hi/lo)
    reduce_g<<<(4 * (int)cc) / 256, 256>>>(gpart, Gh, Gl);

    // 4) P1_b = Wk @ G_b  (G symmetric)  [bf16x3, fp32 out]
    gemm_tcz<<<dim3(4, 4, 4), 128, kYSmem>>>(
        wkh, wkl, 0, Gh, Gl, cc, P1, nullptr, kC, cc);

    // 5) logits + softmax -> attn
    logits_softmax<<<dim3(8, 4), 256>>>(P1, Wqkv, attn);

    // 6) Wht_b = (attn_h @ Wq_h)^T  -> bf16 hi/lo
    what_t<<<dim3(8, 4), 256, kWhatSmem>>>(attn, Wqkv, whth, whtl);

    // 7) Wt_b = Wproj @ Wht_b^T  [bf16x3, fp16 single out]
    gemm_tcz<<<dim3(4, 4, 4), 128, kYSmem>>>(
        wph, wpl, 0, whth, whtl, cc, nullptr, wt16, kC, cc);

    // 8) y = X @ Wt_b^T + bproj  [fp16x2]
    gemm_y16<<<dim3(4, kTok / 128, 4), 128, kY2Smem>>>(
        xh16, xl16, wt16, bproj, out);
}

// round 14
// speedup vs baseline: 1.4791x; 1.1455x over previous
#include <cuda_runtime.h>
#include <cuda_bf16.h>
#include <cuda_fp16.h>
#include <cstdint>
#include <cstddef>

// ---------------------------------------------------------------------------
// ChannelAttention via Gram factorization.
//   G_b   = X_b^T X_b          (fp16x2 mma: A-split, B-single; split-K 8)
//   P1_b  = Wk @ G_b           (bf16x3 mma)
//   logit = softmax(SCALE * P1_h @ Wv_h^T)   (FFMA, tiny)
//   Wht_b = (attn_h @ Wq_h)^T                (FFMA, tiny, emits bf16 hi/lo)
//   Wt_b  = Wproj @ Wht_b^T                  (bf16x3 mma, emits fp16 single)
//   y     = X @ Wt_b^T + bproj               (fp16 single x single mma)
// Round 14: y-GEMM drops the A-split (fp16x2 -> fp16x1). Error adds ~2.4e-4
// unamplified on the output; halves the largest stage's MMA work.
// ---------------------------------------------------------------------------

static constexpr int   kTok   = 8192;
static constexpr int   kC     = 512;
static constexpr int   kM     = 4 * kTok;       // 32768
static constexpr float kScale = 0.125f;
static constexpr int   kSplitK = 8;             // gram split-K
static constexpr int   kKS     = kTok / kSplitK;  // 1024 tokens per split

// Scratch (device globals; all read locations rewritten each launch)
__device__ __half g_xh16[(size_t)kM * kC];
__device__ __half g_xl16[(size_t)kM * kC];
__device__ float g_gpart[(size_t)kSplitK * 4 * kC * kC];
__device__ __nv_bfloat16 g_Gh [(size_t)4 * kC * kC];
__device__ __nv_bfloat16 g_Gl [(size_t)4 * kC * kC];
__device__ float g_P1   [(size_t)4 * kC * kC];
__device__ float g_attn [(size_t)32 * 64 * 64];
__device__ __nv_bfloat16 g_whth[(size_t)4 * kC * kC];
__device__ __nv_bfloat16 g_whtl[(size_t)4 * kC * kC];
__device__ __half g_wt16[(size_t)4 * kC * kC];
__device__ __nv_bfloat16 g_wkh[(size_t)kC * kC];
__device__ __nv_bfloat16 g_wkl[(size_t)kC * kC];
__device__ __nv_bfloat16 g_wph[(size_t)kC * kC];
__device__ __nv_bfloat16 g_wpl[(size_t)kC * kC];

// ---------------------------------------------------------------------------
// primitives
// ---------------------------------------------------------------------------
__device__ __forceinline__ void ldsm_x4(uint32_t addr, uint32_t* r)
{
    asm volatile("ldmatrix.sync.aligned.m8n8.x4.shared.b16 {%0,%1,%2,%3}, [%4];\n"
                 : "=r"(r[0]), "=r"(r[1]), "=r"(r[2]), "=r"(r[3]) : "r"(addr));
}
__device__ __forceinline__ void ldsm_x4_t(uint32_t addr, uint32_t* r)
{
    asm volatile("ldmatrix.sync.aligned.m8n8.x4.trans.shared.b16 {%0,%1,%2,%3}, [%4];\n"
                 : "=r"(r[0]), "=r"(r[1]), "=r"(r[2]), "=r"(r[3]) : "r"(addr));
}
__device__ __forceinline__ void mma_bf16(float* c, const uint32_t* a,
                                         uint32_t b0, uint32_t b1)
{
    asm volatile(
        "mma.sync.aligned.m16n8k16.row.col.f32.bf16.bf16.f32 "
        "{%0,%1,%2,%3}, {%4,%5,%6,%7}, {%8,%9}, {%0,%1,%2,%3};\n"
        : "+f"(c[0]), "+f"(c[1]), "+f"(c[2]), "+f"(c[3])
        : "r"(a[0]), "r"(a[1]), "r"(a[2]), "r"(a[3]), "r"(b0), "r"(b1));
}
__device__ __forceinline__ void mma_f16(float* c, const uint32_t* a,
                                        uint32_t b0, uint32_t b1)
{
    asm volatile(
        "mma.sync.aligned.m16n8k16.row.col.f32.f16.f16.f32 "
        "{%0,%1,%2,%3}, {%4,%5,%6,%7}, {%8,%9}, {%0,%1,%2,%3};\n"
        : "+f"(c[0]), "+f"(c[1]), "+f"(c[2]), "+f"(c[3])
        : "r"(a[0]), "r"(a[1]), "r"(a[2]), "r"(a[3]), "r"(b0), "r"(b1));
}
__device__ __forceinline__ void cp16(uint32_t dst, const void* src)
{
    asm volatile("cp.async.cg.shared.global [%0], [%1], 16;\n" :: "r"(dst), "l"(src));
}
__device__ __forceinline__ void cp_commit()
{
    asm volatile("cp.async.commit_group;\n");
}
template <int N> __device__ __forceinline__ void cp_wait()
{
    asm volatile("cp.async.wait_group %0;\n" :: "n"(N));
}
__device__ __forceinline__ uint32_t pack_h2(float a, float b)
{
    __half2 p;
    p.x = __float2half_rn(a);
    p.y = __float2half_rn(b);
    return *reinterpret_cast<uint32_t*>(&p);
}

// ---------------------------------------------------------------------------
// fp32 -> (hi, lo) bf16 split
// ---------------------------------------------------------------------------
__global__ __launch_bounds__(256) void split_f32(
    const float* __restrict__ src,
    __nv_bfloat16* __restrict__ hi, __nv_bfloat16* __restrict__ lo, int n4)
{
    int i = blockIdx.x * blockDim.x + threadIdx.x;
    if (i >= n4) return;
    float4 f = ((const float4*)src)[i];
    float a[4] = {f.x, f.y, f.z, f.w};
    __nv_bfloat16 h[4], l[4];
#pragma unroll
    for (int j = 0; j < 4; j++) {
        h[j] = __float2bfloat16_rn(a[j]);
        l[j] = __float2bfloat16_rn(a[j] - __bfloat162float(h[j]));
    }
    ((uint2*)hi)[i] = *(uint2*)h;
    ((uint2*)lo)[i] = *(uint2*)l;
}

// fp32 -> (hi, lo) fp16 split
__global__ __launch_bounds__(256) void split_f16(
    const float* __restrict__ src,
    __half* __restrict__ hi, __half* __restrict__ lo, int n4)
{
    int i = blockIdx.x * blockDim.x + threadIdx.x;
    if (i >= n4) return;
    float4 f = ((const float4*)src)[i];
    float a[4] = {f.x, f.y, f.z, f.w};
    __half h[4], l[4];
#pragma unroll
    for (int j = 0; j < 4; j++) {
        h[j] = __float2half_rn(a[j]);
        l[j] = __float2half_rn(a[j] - __half2float(h[j]));
    }
    ((uint2*)hi)[i] = *(uint2*)h;
    ((uint2*)lo)[i] = *(uint2*)l;
}

// ---------------------------------------------------------------------------
// Gram partials (fp16x2: A split hi/lo, B single hi), split-K 8, BK=16,
// 3-stage. 128 threads, 4 warps of 64x64, CTA 128x128 upper-tri pairs.
// Stage: Ah | Al | Bh, each 16 rows x 136 fp16 = 4352 B -> 13056 B.
// ---------------------------------------------------------------------------
static constexpr int kGArr      = 16 * 136 * 2;       // 4352 B
static constexpr int kGramStage = 3 * kGArr;          // 13056 B
static constexpr int kGramSmem  = 3 * kGramStage;     // 39168 B

__global__ __launch_bounds__(128, 2) void gemm_gram16(
    const __half* __restrict__ Xhi,
    const __half* __restrict__ Xlo,
    float* __restrict__ part)
{
    extern __shared__ __align__(16) char smem[];
    const uint32_t sbase = (uint32_t)__cvta_generic_to_shared(smem);

    int p = blockIdx.x, mb = 0;
    while (p >= 4 - mb) { p -= 4 - mb; mb++; }
    const int m0 = mb * 128, n0 = (mb + p) * 128;
    const int bz = blockIdx.y;           // b*kSplitK + s
    const int b = bz >> 3, s = bz & 7;
    const size_t tokBase = (size_t)b * kTok + (size_t)s * kKS;

    const int tid = threadIdx.x, wid = tid >> 5, lane = tid & 31;
    const int wm = (wid >> 1) * 64, wn = (wid & 1) * 64;

    const int lr0 = tid >> 3;              // row 0..15
    const int ch0 = (tid & 7) * 16;        // chunk cols ch0, ch0+8

    auto issue = [&](int kt) {
        const uint32_t stg = sbase + (uint32_t)(kt % 3) * kGramStage;
        const size_t ro = (tokBase + (size_t)kt * 16 + lr0) * kC;
#pragma unroll
        for (int cg = 0; cg < 2; cg++) {
            const int ch = ch0 + cg * 8;
            const uint32_t d = (uint32_t)(lr0 * 136 + ch) * 2;
            cp16(stg +             d, Xhi + ro + m0 + ch);
            cp16(stg +     kGArr + d, Xlo + ro + m0 + ch);
            cp16(stg + 2 * kGArr + d, Xhi + ro + n0 + ch);
        }
        cp_commit();
    };

    const int kA = (lane & 7) + ((lane >> 4) & 1) * 8;
    const int mA = ((lane >> 3) & 1) * 8;
    const int kB = (lane & 7) + ((lane >> 3) & 1) * 8;
    const int nB = ((lane >> 4) & 1) * 8;

    float acc[4][8][4];
#pragma unroll
    for (int mt = 0; mt < 4; mt++)
#pragma unroll
        for (int nt = 0; nt < 8; nt++)
#pragma unroll
            for (int i = 0; i < 4; i++) acc[mt][nt][i] = 0.f;

    const int NK = kKS / 16;   // 64
    issue(0); issue(1);

#pragma unroll 1
    for (int kt = 0; kt < NK; kt++) {
        cp_wait<1>();
        __syncthreads();
        if (kt + 2 < NK) issue(kt + 2);
        else             cp_commit();

        const uint32_t stg = sbase + (uint32_t)(kt % 3) * kGramStage;
        uint32_t ahi[4][4], alo[4][4];
#pragma unroll
        for (int mt = 0; mt < 4; mt++) {
            const uint32_t co = (uint32_t)(kA * 136 + wm + mt * 16 + mA) * 2;
            ldsm_x4_t(stg +         co, ahi[mt]);
            ldsm_x4_t(stg + kGArr + co, alo[mt]);
        }
#pragma unroll
        for (int ng = 0; ng < 4; ng++) {
            uint32_t bh[4];
            const uint32_t co = (uint32_t)(kB * 136 + wn + ng * 16 + nB) * 2;
            ldsm_x4_t(stg + 2 * kGArr + co, bh);
#pragma unroll
            for (int mt = 0; mt < 4; mt++) {
#pragma unroll
                for (int j = 0; j < 2; j++) {
                    float* c = acc[mt][ng * 2 + j];
                    mma_f16(c, ahi[mt], bh[2 * j], bh[2 * j + 1]);
                    mma_f16(c, alo[mt], bh[2 * j], bh[2 * j + 1]);
                }
            }
        }
    }

    const int g = lane >> 2, tg = lane & 3;
    float* P = part + (size_t)(s * 4 + b) * kC * kC;
#pragma unroll
    for (int mt = 0; mt < 4; mt++) {
#pragma unroll
        for (int nt = 0; nt < 8; nt++) {
            const int r   = m0 + wm + mt * 16 + g;
            const int col = n0 + wn + nt * 8 + tg * 2;
            *(float2*)(P + (size_t)r * kC + col) =
                make_float2(acc[mt][nt][0], acc[mt][nt][1]);
            *(float2*)(P + (size_t)(r + 8) * kC + col) =
                make_float2(acc[mt][nt][2], acc[mt][nt][3]);
        }
    }
}

// ---------------------------------------------------------------------------
// Reduce split-K partials with symmetric mirroring -> G as bf16 hi/lo.
// ---------------------------------------------------------------------------
__global__ __launch_bounds__(256) void reduce_g(
    const float* __restrict__ part,
    __nv_bfloat16* __restrict__ Gh, __nv_bfloat16* __restrict__ Gl)
{
    const int i = blockIdx.x * 256 + threadIdx.x;
    const int b = i >> 18;
    const int r = (i >> 9) & 511;
    const int c = i & 511;
    const size_t src = ((r >> 7) <= (c >> 7))
        ? ((size_t)r * kC + c) : ((size_t)c * kC + r);
    float sum = 0.f;
#pragma unroll
    for (int s = 0; s < kSplitK; s++)
        sum += part[(size_t)(s * 4 + b) * kC * kC + src];
    const size_t o = (size_t)b * kC * kC + (size_t)r * kC + c;
    __nv_bfloat16 h = __float2bfloat16_rn(sum);
    Gh[o] = h;
    Gl[o] = __float2bfloat16_rn(sum - __bfloat162float(h));
}

// ---------------------------------------------------------------------------
// bf16x3 tensor GEMM (middle GEMMs): C = A @ B^T, CTA 128x128 (4 warps of
// 64x64), K=512, batched over z, BK=16, 3-stage.
// outF -> fp32 out, else out16 -> fp16 single out.
// Stage: Ah|Al|Bh|Bl each 128 rows x 24 bf16 = 6144 B -> 24576 B.
// ---------------------------------------------------------------------------
static constexpr int kYArr   = 128 * 24 * 2;   // 6144 B
static constexpr int kYStage = 4 * kYArr;      // 24576 B
static constexpr int kYSmem  = 3 * kYStage;    // 73728 B

__global__ __launch_bounds__(128, 2) void gemm_tcz(
    const __nv_bfloat16* __restrict__ Ahi, const __nv_bfloat16* __restrict__ Alo,
    size_t strideA,
    const __nv_bfloat16* __restrict__ Bhi, const __nv_bfloat16* __restrict__ Blo,
    size_t strideB,
    float* __restrict__ outF,
    __half* __restrict__ out16,
    int ldc, size_t strideC)
{
    extern __shared__ __align__(16) char smem[];
    const uint32_t sbase = (uint32_t)__cvta_generic_to_shared(smem);

    const int tid = threadIdx.x, wid = tid >> 5, lane = tid & 31;
    const int n0 = blockIdx.x * 128;
    const int m0 = blockIdx.y * 128;
    const int z  = blockIdx.z;
    const int wm = (wid >> 1) * 64, wn = (wid & 1) * 64;

    const __nv_bfloat16* Ah = Ahi + strideA * z + (size_t)m0 * kC;
    const __nv_bfloat16* Al = Alo + strideA * z + (size_t)m0 * kC;
    const __nv_bfloat16* Bh = Bhi + strideB * z + (size_t)n0 * kC;
    const __nv_bfloat16* Bl = Blo + strideB * z + (size_t)n0 * kC;

    const int lr0 = tid >> 1;           // rows lr0, lr0+64
    const int lk8 = (tid & 1) * 8;      // 0 or 8

    auto issue = [&](int kt) {
        const uint32_t stg = sbase + (uint32_t)(kt % 3) * kYStage;
#pragma unroll
        for (int half = 0; half < 2; half++) {
            const int row = lr0 + half * 64;
            const uint32_t d = (uint32_t)(row * 24 + lk8) * 2;
            const size_t ro = (size_t)row * kC + kt * 16 + lk8;
            cp16(stg +             d, Ah + ro);
            cp16(stg +     kYArr + d, Al + ro);
            cp16(stg + 2 * kYArr + d, Bh + ro);
            cp16(stg + 3 * kYArr + d, Bl + ro);
        }
        cp_commit();
    };

    const int aRow = lane & 15;
    const int aKof = (lane >> 4) * 8;
    const int bRow = (lane & 7) + ((lane >> 4) & 1) * 8;
    const int bKof = ((lane >> 3) & 1) * 8;

    float acc[4][8][4];
#pragma unroll
    for (int mt = 0; mt < 4; mt++)
#pragma unroll
        for (int nt = 0; nt < 8; nt++)
#pragma unroll
            for (int i = 0; i < 4; i++) acc[mt][nt][i] = 0.f;

    const int NK = kC / 16;   // 32
    issue(0); issue(1);

#pragma unroll 1
    for (int kt = 0; kt < NK; kt++) {
        cp_wait<1>();
        __syncthreads();
        if (kt + 2 < NK) issue(kt + 2);
        else             cp_commit();

        const uint32_t stg = sbase + (uint32_t)(kt % 3) * kYStage;
        uint32_t ahi[4][4], alo[4][4];
#pragma unroll
        for (int mt = 0; mt < 4; mt++) {
            const uint32_t co = (uint32_t)((wm + mt * 16 + aRow) * 24 + aKof) * 2;
            ldsm_x4(stg +         co, ahi[mt]);
            ldsm_x4(stg + kYArr + co, alo[mt]);
        }
#pragma unroll
        for (int ng = 0; ng < 4; ng++) {
            uint32_t bh[4], bl[4];
            const uint32_t co = (uint32_t)((wn + ng * 16 + bRow) * 24 + bKof) * 2;
            ldsm_x4(stg + 2 * kYArr + co, bh);
            ldsm_x4(stg + 3 * kYArr + co, bl);
#pragma unroll
            for (int mt = 0; mt < 4; mt++) {
#pragma unroll
                for (int j = 0; j < 2; j++) {
                    float* c = acc[mt][ng * 2 + j];
                    mma_bf16(c, ahi[mt], bh[2 * j], bh[2 * j + 1]);
                    mma_bf16(c, ahi[mt], bl[2 * j], bl[2 * j + 1]);
                    mma_bf16(c, alo[mt], bh[2 * j], bh[2 * j + 1]);
                }
            }
        }
    }

    const int g = lane >> 2, tg = lane & 3;
#pragma unroll
    for (int mt = 0; mt < 4; mt++) {
#pragma unroll
        for (int nt = 0; nt < 8; nt++) {
            const int r   = m0 + wm + mt * 16 + g;
            const int col = n0 + wn + nt * 8 + tg * 2;
            const float v0 = acc[mt][nt][0], v1 = acc[mt][nt][1];
            const float v2 = acc[mt][nt][2], v3 = acc[mt][nt][3];
            const size_t o0 = strideC * z + (size_t)r * ldc + col;
            const size_t o1 = strideC * z + (size_t)(r + 8) * ldc + col;
            if (outF) {
                *(float2*)(outF + o0) = make_float2(v0, v1);
                *(float2*)(outF + o1) = make_float2(v2, v3);
            } else {
                *(uint32_t*)(out16 + o0) = pack_h2(v0, v1);
                *(uint32_t*)(out16 + o1) = pack_h2(v2, v3);
            }
        }
    }
}

// ---------------------------------------------------------------------------
// fp16 single x single GEMM (y): C = A @ B^T + bias.
// CTA 128x128 (4 warps of 64x64), K=512, batched over z, BK=16, 3-stage.
// Stage: Ah|Bh each 128 rows x 24 fp16 = 6144 B -> 12288 B.
// ---------------------------------------------------------------------------
static constexpr int kY1Stage = 2 * kYArr;      // 12288 B
static constexpr int kY1Smem  = 3 * kY1Stage;   // 36864 B

__global__ __launch_bounds__(128, 2) void gemm_y16s(
    const __half* __restrict__ A16,
    const __half* __restrict__ B16,
    const float* __restrict__ bias, float* __restrict__ C)
{
    extern __shared__ __align__(16) char smem[];
    const uint32_t sbase = (uint32_t)__cvta_generic_to_shared(smem);

    const int tid = threadIdx.x, wid = tid >> 5, lane = tid & 31;
    const int n0 = blockIdx.x * 128;
    const int m0 = blockIdx.y * 128;
    const int z  = blockIdx.z;
    const int wm = (wid >> 1) * 64, wn = (wid & 1) * 64;

    const __half* Ah = A16 + ((size_t)z * kTok + m0) * kC;
    const __half* Bh = B16 + (size_t)z * kC * kC + (size_t)n0 * kC;

    const int lr0 = tid >> 1;
    const int lk8 = (tid & 1) * 8;

    auto issue = [&](int kt) {
        const uint32_t stg = sbase + (uint32_t)(kt % 3) * kY1Stage;
#pragma unroll
        for (int half = 0; half < 2; half++) {
            const int row = lr0 + half * 64;
            const uint32_t d = (uint32_t)(row * 24 + lk8) * 2;
            const size_t ro = (size_t)row * kC + kt * 16 + lk8;
            cp16(stg +         d, Ah + ro);
            cp16(stg + kYArr + d, Bh + ro);
        }
        cp_commit();
    };

    const int aRow = lane & 15;
    const int aKof = (lane >> 4) * 8;
    const int bRow = (lane & 7) + ((lane >> 4) & 1) * 8;
    const int bKof = ((lane >> 3) & 1) * 8;

    float acc[4][8][4];
#pragma unroll
    for (int mt = 0; mt < 4; mt++)
#pragma unroll
        for (int nt = 0; nt < 8; nt++)
#pragma unroll
            for (int i = 0; i < 4; i++) acc[mt][nt][i] = 0.f;

    const int NK = kC / 16;   // 32
    issue(0); issue(1);

#pragma unroll 1
    for (int kt = 0; kt < NK; kt++) {
        cp_wait<1>();
        __syncthreads();
        if (kt + 2 < NK) issue(kt + 2);
        else             cp_commit();

        const uint32_t stg = sbase + (uint32_t)(kt % 3) * kY1Stage;
        uint32_t ah[4][4];
#pragma unroll
        for (int mt = 0; mt < 4; mt++) {
            const uint32_t co = (uint32_t)((wm + mt * 16 + aRow) * 24 + aKof) * 2;
            ldsm_x4(stg + co, ah[mt]);
        }
#pragma unroll
        for (int ng = 0; ng < 4; ng++) {
            uint32_t bh[4];
            const uint32_t co = (uint32_t)((wn + ng * 16 + bRow) * 24 + bKof) * 2;
            ldsm_x4(stg + kYArr + co, bh);
#pragma unroll
            for (int mt = 0; mt < 4; mt++) {
#pragma unroll
                for (int j = 0; j < 2; j++) {
                    mma_f16(acc[mt][ng * 2 + j], ah[mt],
                            bh[2 * j], bh[2 * j + 1]);
                }
            }
        }
    }

    const int g = lane >> 2, tg = lane & 3;
#pragma unroll
    for (int mt = 0; mt < 4; mt++) {
#pragma unroll
        for (int nt = 0; nt < 8; nt++) {
            const int r   = m0 + wm + mt * 16 + g;
            const int col = n0 + wn + nt * 8 + tg * 2;
            const float b0 = bias[col], b1 = bias[col + 1];
            float* crow = C + ((size_t)z * kTok + r) * kC + col;
            *(float2*)(crow) =
                make_float2(acc[mt][nt][0] + b0, acc[mt][nt][1] + b1);
            *(float2*)(crow + (size_t)8 * kC) =
                make_float2(acc[mt][nt][2] + b0, acc[mt][nt][3] + b1);
        }
    }
}

// ---------------------------------------------------------------------------
// logits_h = SCALE * P1_h @ Wv_h^T (64x64, K=512), row softmax -> attn.
// ---------------------------------------------------------------------------
__global__ __launch_bounds__(256) void logits_softmax(
    const float* __restrict__ P1, const float* __restrict__ Wqkv,
    float* __restrict__ attn)
{
    const int h = blockIdx.x, b = blockIdx.y;
    const float* p1 = P1 + (size_t)b * kC * kC + (size_t)(h * 64) * kC;
    const float* wv = Wqkv + (size_t)(1024 + h * 64) * kC;

    __shared__ float ps[16][68];
    __shared__ float vs[16][68];
    __shared__ float ls[64][68];

    const int tid = threadIdx.x;
    const int ty = tid >> 4, tx = tid & 15;
    const int lr = tid >> 2, lc = (tid & 3) * 4;

    float acc[4][4];
#pragma unroll
    for (int i = 0; i < 4; i++)
#pragma unroll
        for (int j = 0; j < 4; j++) acc[i][j] = 0.f;

    for (int c0 = 0; c0 < kC; c0 += 16) {
        float4 pv = *(const float4*)(p1 + (size_t)lr * kC + c0 + lc);
        float4 vv = *(const float4*)(wv + (size_t)lr * kC + c0 + lc);
        __syncthreads();
        ps[lc+0][lr]=pv.x; ps[lc+1][lr]=pv.y; ps[lc+2][lr]=pv.z; ps[lc+3][lr]=pv.w;
        vs[lc+0][lr]=vv.x; vs[lc+1][lr]=vv.y; vs[lc+2][lr]=vv.z; vs[lc+3][lr]=vv.w;
        __syncthreads();
#pragma unroll
        for (int cc = 0; cc < 16; cc++) {
            float a[4], v[4];
#pragma unroll
            for (int i = 0; i < 4; i++) a[i] = ps[cc][ty * 4 + i];
#pragma unroll
            for (int j = 0; j < 4; j++) v[j] = vs[cc][tx * 4 + j];
#pragma unroll
            for (int i = 0; i < 4; i++)
#pragma unroll
                for (int j = 0; j < 4; j++)
                    acc[i][j] += a[i] * v[j];
        }
    }

    __syncthreads();
#pragma unroll
    for (int i = 0; i < 4; i++)
#pragma unroll
        for (int j = 0; j < 4; j++)
            ls[ty * 4 + i][tx * 4 + j] = acc[i][j];
    __syncthreads();

    const int warp = tid >> 5, lane = tid & 31;
    float* arow_base = attn + (size_t)(b * 8 + h) * 4096;
    for (int r = 0; r < 8; r++) {
        const int d = warp * 8 + r;
        float v1 = kScale * ls[d][lane];
        float v2 = kScale * ls[d][lane + 32];
        float m = fmaxf(v1, v2);
#pragma unroll
        for (int s = 16; s > 0; s >>= 1)
            m = fmaxf(m, __shfl_xor_sync(0xffffffffu, m, s));
        float e1 = expf(v1 - m), e2 = expf(v2 - m);
        float sm = e1 + e2;
#pragma unroll
        for (int s = 16; s > 0; s >>= 1)
            sm += __shfl_xor_sync(0xffffffffu, sm, s);
        float inv = 1.f / sm;
        arow_base[d * 64 + lane]      = e1 * inv;
        arow_base[d * 64 + lane + 32] = e2 * inv;
    }
}

// ---------------------------------------------------------------------------
// Wht_b[c][h*64+d] = sum_e attn_h[d,e] * Wq[h*64+e][c] -> bf16 hi/lo.
// ---------------------------------------------------------------------------
static constexpr int kWhatSmem = (64 * 68 + 64 * 132) * 4;

__device__ __forceinline__ uint32_t pack_hi2b(float a, float b)
{
    __nv_bfloat162 p;
    p.x = __float2bfloat16_rn(a);
    p.y = __float2bfloat16_rn(b);
    return *reinterpret_cast<uint32_t*>(&p);
}
__device__ __forceinline__ uint32_t pack_lo2b(float a, float b, uint32_t hi)
{
    __nv_bfloat162 h = *reinterpret_cast<__nv_bfloat162*>(&hi);
    __nv_bfloat162 p;
    p.x = __float2bfloat16_rn(a - __bfloat162float(h.x));
    p.y = __float2bfloat16_rn(b - __bfloat162float(h.y));
    return *reinterpret_cast<uint32_t*>(&p);
}

__global__ __launch_bounds__(256) void what_t(
    const float* __restrict__ attn, const float* __restrict__ Wqkv,
    __nv_bfloat16* __restrict__ whth, __nv_bfloat16* __restrict__ whtl)
{
    extern __shared__ __align__(16) float ws[];
    float (*at)[68]  = (float(*)[68])ws;
    float (*wq)[132] = (float(*)[132])(ws + 64 * 68);

    const int h = blockIdx.x, b = blockIdx.y;
    const float* ag = attn + (size_t)(b * 8 + h) * 4096;
    const float* Wq = Wqkv + (size_t)(h * 64) * kC;
    const size_t obase = (size_t)b * kC * kC;

    const int tid = threadIdx.x;
    for (int i = tid; i < 4096; i += 256)
        at[i >> 6][i & 63] = ag[i];

    const int dG = (tid & 15) * 4;
    const int cB = tid >> 4;

    for (int cb = 0; cb < 4; cb++) {
        __syncthreads();
        for (int i = 0; i < 8; i++) {
            const int f4 = tid + i * 256;
            const int e  = f4 >> 5;
            const int cq = (f4 & 31) * 4;
            *(float4*)&wq[e][cq] =
                *(const float4*)(Wq + (size_t)e * kC + cb * 128 + cq);
        }
        __syncthreads();

        float o[8][4];
#pragma unroll
        for (int i = 0; i < 8; i++)
#pragma unroll
            for (int j = 0; j < 4; j++) o[i][j] = 0.f;

#pragma unroll 4
        for (int e = 0; e < 64; e++) {
            float a[4], w[8];
#pragma unroll
            for (int j = 0; j < 4; j++) a[j] = at[dG + j][e];
#pragma unroll
            for (int i = 0; i < 8; i++) w[i] = wq[e][cB * 8 + i];
#pragma unroll
            for (int i = 0; i < 8; i++)
#pragma unroll
                for (int j = 0; j < 4; j++)
                    o[i][j] += w[i] * a[j];
        }

#pragma unroll
        for (int i = 0; i < 8; i++) {
            const int c = cb * 128 + cB * 8 + i;
            const size_t oo = obase + (size_t)c * kC + h * 64 + dG;
            uint32_t h0 = pack_hi2b(o[i][0], o[i][1]);
            uint32_t h1 = pack_hi2b(o[i][2], o[i][3]);
            uint32_t l0 = pack_lo2b(o[i][0], o[i][1], h0);
            uint32_t l1 = pack_lo2b(o[i][2], o[i][3], h1);
            ((uint32_t*)(whth + oo))[0] = h0;
            ((uint32_t*)(whth + oo))[1] = h1;
            ((uint32_t*)(whtl + oo))[0] = l0;
            ((uint32_t*)(whtl + oo))[1] = l1;
        }
    }
}

// ---------------------------------------------------------------------------
extern "C" void kernel_launch(void* const* d_in, const int* in_sizes, int n_in,
                              void* d_out, int out_size)
{
    const float* x     = (const float*)d_in[0];
    const float* Wqkv  = (const float*)d_in[1];
    const float* Wproj = (const float*)d_in[2];
    const float* bproj = (const float*)d_in[3];
    float* out = (float*)d_out;

    __half *xh16, *xl16, *wt16;
    __nv_bfloat16 *Gh, *Gl, *whth, *whtl, *wkh, *wkl, *wph, *wpl;
    float *gpart, *P1, *attn;
    cudaGetSymbolAddress((void**)&xh16,  g_xh16);
    cudaGetSymbolAddress((void**)&xl16,  g_xl16);
    cudaGetSymbolAddress((void**)&gpart, g_gpart);
    cudaGetSymbolAddress((void**)&Gh,    g_Gh);
    cudaGetSymbolAddress((void**)&Gl,    g_Gl);
    cudaGetSymbolAddress((void**)&P1,    g_P1);
    cudaGetSymbolAddress((void**)&attn,  g_attn);
    cudaGetSymbolAddress((void**)&whth,  g_whth);
    cudaGetSymbolAddress((void**)&whtl,  g_whtl);
    cudaGetSymbolAddress((void**)&wt16,  g_wt16);
    cudaGetSymbolAddress((void**)&wkh,   g_wkh);
    cudaGetSymbolAddress((void**)&wkl,   g_wkl);
    cudaGetSymbolAddress((void**)&wph,   g_wph);
    cudaGetSymbolAddress((void**)&wpl,   g_wpl);

    cudaFuncSetAttribute(gemm_gram16,
        cudaFuncAttributeMaxDynamicSharedMemorySize, kGramSmem);
    cudaFuncSetAttribute(what_t,
        cudaFuncAttributeMaxDynamicSharedMemorySize, kWhatSmem);
    cudaFuncSetAttribute(gemm_tcz,
        cudaFuncAttributeMaxDynamicSharedMemorySize, kYSmem);
    cudaFuncSetAttribute(gemm_y16s,
        cudaFuncAttributeMaxDynamicSharedMemorySize, kY1Smem);

    const size_t cc = (size_t)kC * kC;

    // 1) splits: X -> fp16 hi/lo; Wk, Wproj -> bf16 hi/lo
    split_f16<<<(kM * kC / 4 + 255) / 256, 256>>>(x, xh16, xl16, kM * kC / 4);
    split_f32<<<((int)cc / 4 + 255) / 256, 256>>>(Wqkv + cc, wkh, wkl, (int)cc / 4);
    split_f32<<<((int)cc / 4 + 255) / 256, 256>>>(Wproj, wph, wpl, (int)cc / 4);

    // 2) Gram partials (fp16x2, split-K 8)
    gemm_gram16<<<dim3(10, 4 * kSplitK), 128, kGramSmem>>>(xh16, xl16, gpart);

    // 3) reduce + mirror -> G (bf16 hi/lo)
    reduce_g<<<(4 * (int)cc) / 256, 256>>>(gpart, Gh, Gl);

    // 4) P1_b = Wk @ G_b  (G symmetric)  [bf16x3, fp32 out]
    gemm_tcz<<<dim3(4, 4, 4), 128, kYSmem>>>(
        wkh, wkl, 0, Gh, Gl, cc, P1, nullptr, kC, cc);

    // 5) logits + softmax -> attn
    logits_softmax<<<dim3(8, 4), 256>>>(P1, Wqkv, attn);

    // 6) Wht_b = (attn_h @ Wq_h)^T  -> bf16 hi/lo
    what_t<<<dim3(8, 4), 256, kWhatSmem>>>(attn, Wqkv, whth, whtl);

    // 7) Wt_b = Wproj @ Wht_b^T  [bf16x3, fp16 single out]
    gemm_tcz<<<dim3(4, 4, 4), 128, kYSmem>>>(
        wph, wpl, 0, whth, whtl, cc, nullptr, wt16, kC, cc);

    // 8) y = X @ Wt_b^T + bproj  [fp16 single x single]
    gemm_y16s<<<dim3(4, kTok / 128, 4), 128, kY1Smem>>>(
        xh16, wt16, bproj, out);
}

// round 16
// speedup vs baseline: 1.6375x; 1.1070x over previous
#include <cuda_runtime.h>
#include <cuda_bf16.h>
#include <cuda_fp16.h>
#include <cstdint>
#include <cstddef>

// ---------------------------------------------------------------------------
// ChannelAttention via Gram factorization.
//   G_b   = X_b^T X_b          (fp16 single x single mma; split-K 8)
//   P1_b  = Wk @ G_b           (bf16x3 mma)
//   logit = softmax(SCALE * P1_h @ Wv_h^T)   (FFMA, tiny)
//   Wht_b = (attn_h @ Wq_h)^T                (FFMA, tiny, emits bf16 hi/lo)
//   Wt_b  = Wproj @ Wht_b^T                  (bf16x3 mma, emits fp16 single)
//   y     = X @ Wt_b^T + bproj               (fp16 single x single mma)
// Round 16 (= round 15 resubmitted after infra failure): gram drops the
// A-split (fp16x2 -> fp16x1); X converted to a single fp16 array.
// ---------------------------------------------------------------------------

static constexpr int   kTok   = 8192;
static constexpr int   kC     = 512;
static constexpr int   kM     = 4 * kTok;       // 32768
static constexpr float kScale = 0.125f;
static constexpr int   kSplitK = 8;             // gram split-K
static constexpr int   kKS     = kTok / kSplitK;  // 1024 tokens per split

// Scratch (device globals; all read locations rewritten each launch)
__device__ __half g_x16 [(size_t)kM * kC];
__device__ float g_gpart[(size_t)kSplitK * 4 * kC * kC];
__device__ __nv_bfloat16 g_Gh [(size_t)4 * kC * kC];
__device__ __nv_bfloat16 g_Gl [(size_t)4 * kC * kC];
__device__ float g_P1   [(size_t)4 * kC * kC];
__device__ float g_attn [(size_t)32 * 64 * 64];
__device__ __nv_bfloat16 g_whth[(size_t)4 * kC * kC];
__device__ __nv_bfloat16 g_whtl[(size_t)4 * kC * kC];
__device__ __half g_wt16[(size_t)4 * kC * kC];
__device__ __nv_bfloat16 g_wkh[(size_t)kC * kC];
__device__ __nv_bfloat16 g_wkl[(size_t)kC * kC];
__device__ __nv_bfloat16 g_wph[(size_t)kC * kC];
__device__ __nv_bfloat16 g_wpl[(size_t)kC * kC];

// ---------------------------------------------------------------------------
// primitives
// ---------------------------------------------------------------------------
__device__ __forceinline__ void ldsm_x4(uint32_t addr, uint32_t* r)
{
    asm volatile("ldmatrix.sync.aligned.m8n8.x4.shared.b16 {%0,%1,%2,%3}, [%4];\n"
                 : "=r"(r[0]), "=r"(r[1]), "=r"(r[2]), "=r"(r[3]) : "r"(addr));
}
__device__ __forceinline__ void ldsm_x4_t(uint32_t addr, uint32_t* r)
{
    asm volatile("ldmatrix.sync.aligned.m8n8.x4.trans.shared.b16 {%0,%1,%2,%3}, [%4];\n"
                 : "=r"(r[0]), "=r"(r[1]), "=r"(r[2]), "=r"(r[3]) : "r"(addr));
}
__device__ __forceinline__ void mma_bf16(float* c, const uint32_t* a,
                                         uint32_t b0, uint32_t b1)
{
    asm volatile(
        "mma.sync.aligned.m16n8k16.row.col.f32.bf16.bf16.f32 "
        "{%0,%1,%2,%3}, {%4,%5,%6,%7}, {%8,%9}, {%0,%1,%2,%3};\n"
        : "+f"(c[0]), "+f"(c[1]), "+f"(c[2]), "+f"(c[3])
        : "r"(a[0]), "r"(a[1]), "r"(a[2]), "r"(a[3]), "r"(b0), "r"(b1));
}
__device__ __forceinline__ void mma_f16(float* c, const uint32_t* a,
                                        uint32_t b0, uint32_t b1)
{
    asm volatile(
        "mma.sync.aligned.m16n8k16.row.col.f32.f16.f16.f32 "
        "{%0,%1,%2,%3}, {%4,%5,%6,%7}, {%8,%9}, {%0,%1,%2,%3};\n"
        : "+f"(c[0]), "+f"(c[1]), "+f"(c[2]), "+f"(c[3])
        : "r"(a[0]), "r"(a[1]), "r"(a[2]), "r"(a[3]), "r"(b0), "r"(b1));
}
__device__ __forceinline__ void cp16(uint32_t dst, const void* src)
{
    asm volatile("cp.async.cg.shared.global [%0], [%1], 16;\n" :: "r"(dst), "l"(src));
}
__device__ __forceinline__ void cp_commit()
{
    asm volatile("cp.async.commit_group;\n");
}
template <int N> __device__ __forceinline__ void cp_wait()
{
    asm volatile("cp.async.wait_group %0;\n" :: "n"(N));
}
__device__ __forceinline__ uint32_t pack_h2(float a, float b)
{
    __half2 p;
    p.x = __float2half_rn(a);
    p.y = __float2half_rn(b);
    return *reinterpret_cast<uint32_t*>(&p);
}

// ---------------------------------------------------------------------------
// fp32 -> (hi, lo) bf16 split
// ---------------------------------------------------------------------------
__global__ __launch_bounds__(256) void split_f32(
    const float* __restrict__ src,
    __nv_bfloat16* __restrict__ hi, __nv_bfloat16* __restrict__ lo, int n4)
{
    int i = blockIdx.x * blockDim.x + threadIdx.x;
    if (i >= n4) return;
    float4 f = ((const float4*)src)[i];
    float a[4] = {f.x, f.y, f.z, f.w};
    __nv_bfloat16 h[4], l[4];
#pragma unroll
    for (int j = 0; j < 4; j++) {
        h[j] = __float2bfloat16_rn(a[j]);
        l[j] = __float2bfloat16_rn(a[j] - __bfloat162float(h[j]));
    }
    ((uint2*)hi)[i] = *(uint2*)h;
    ((uint2*)lo)[i] = *(uint2*)l;
}

// fp32 -> fp16 convert (single)
__global__ __launch_bounds__(256) void conv_f16(
    const float* __restrict__ src, __half* __restrict__ dst, int n4)
{
    int i = blockIdx.x * blockDim.x + threadIdx.x;
    if (i >= n4) return;
    float4 f = ((const float4*)src)[i];
    __half h[4];
    h[0] = __float2half_rn(f.x);
    h[1] = __float2half_rn(f.y);
    h[2] = __float2half_rn(f.z);
    h[3] = __float2half_rn(f.w);
    ((uint2*)dst)[i] = *(uint2*)h;
}

// ---------------------------------------------------------------------------
// Gram partials (fp16 single x single), split-K 8, BK=16, 3-stage.
// 128 threads, 4 warps of 64x64, CTA 128x128 upper-tri pairs.
// Stage: A | B, each 16 rows x 136 fp16 = 4352 B -> 8704 B.
// ---------------------------------------------------------------------------
static constexpr int kGArr      = 16 * 136 * 2;       // 4352 B
static constexpr int kGramStage = 2 * kGArr;          // 8704 B
static constexpr int kGramSmem  = 3 * kGramStage;     // 26112 B

__global__ __launch_bounds__(128, 2) void gemm_gram16(
    const __half* __restrict__ X16,
    float* __restrict__ part)
{
    extern __shared__ __align__(16) char smem[];
    const uint32_t sbase = (uint32_t)__cvta_generic_to_shared(smem);

    int p = blockIdx.x, mb = 0;
    while (p >= 4 - mb) { p -= 4 - mb; mb++; }
    const int m0 = mb * 128, n0 = (mb + p) * 128;
    const int bz = blockIdx.y;           // b*kSplitK + s
    const int b = bz >> 3, s = bz & 7;
    const size_t tokBase = (size_t)b * kTok + (size_t)s * kKS;

    const int tid = threadIdx.x, wid = tid >> 5, lane = tid & 31;
    const int wm = (wid >> 1) * 64, wn = (wid & 1) * 64;

    const int lr0 = tid >> 3;              // row 0..15
    const int ch0 = (tid & 7) * 16;        // chunk cols ch0, ch0+8

    auto issue = [&](int kt) {
        const uint32_t stg = sbase + (uint32_t)(kt % 3) * kGramStage;
        const size_t ro = (tokBase + (size_t)kt * 16 + lr0) * kC;
#pragma unroll
        for (int cg = 0; cg < 2; cg++) {
            const int ch = ch0 + cg * 8;
            const uint32_t d = (uint32_t)(lr0 * 136 + ch) * 2;
            cp16(stg +         d, X16 + ro + m0 + ch);
            cp16(stg + kGArr + d, X16 + ro + n0 + ch);
        }
        cp_commit();
    };

    // trans fragment lane mapping
    const int kA = (lane & 7) + ((lane >> 4) & 1) * 8;
    const int mA = ((lane >> 3) & 1) * 8;
    const int kB = (lane & 7) + ((lane >> 3) & 1) * 8;
    const int nB = ((lane >> 4) & 1) * 8;

    float acc[4][8][4];
#pragma unroll
    for (int mt = 0; mt < 4; mt++)
#pragma unroll
        for (int nt = 0; nt < 8; nt++)
#pragma unroll
            for (int i = 0; i < 4; i++) acc[mt][nt][i] = 0.f;

    const int NK = kKS / 16;   // 64
    issue(0); issue(1);

#pragma unroll 1
    for (int kt = 0; kt < NK; kt++) {
        cp_wait<1>();
        __syncthreads();
        if (kt + 2 < NK) issue(kt + 2);
        else             cp_commit();

        const uint32_t stg = sbase + (uint32_t)(kt % 3) * kGramStage;
        uint32_t ah[4][4];
#pragma unroll
        for (int mt = 0; mt < 4; mt++) {
            const uint32_t co = (uint32_t)(kA * 136 + wm + mt * 16 + mA) * 2;
            ldsm_x4_t(stg + co, ah[mt]);
        }
#pragma unroll
        for (int ng = 0; ng < 4; ng++) {
            uint32_t bh[4];
            const uint32_t co = (uint32_t)(kB * 136 + wn + ng * 16 + nB) * 2;
            ldsm_x4_t(stg + kGArr + co, bh);
#pragma unroll
            for (int mt = 0; mt < 4; mt++) {
#pragma unroll
                for (int j = 0; j < 2; j++) {
                    mma_f16(acc[mt][ng * 2 + j], ah[mt],
                            bh[2 * j], bh[2 * j + 1]);
                }
            }
        }
    }

    const int g = lane >> 2, tg = lane & 3;
    float* P = part + (size_t)(s * 4 + b) * kC * kC;
#pragma unroll
    for (int mt = 0; mt < 4; mt++) {
#pragma unroll
        for (int nt = 0; nt < 8; nt++) {
            const int r   = m0 + wm + mt * 16 + g;
            const int col = n0 + wn + nt * 8 + tg * 2;
            *(float2*)(P + (size_t)r * kC + col) =
                make_float2(acc[mt][nt][0], acc[mt][nt][1]);
            *(float2*)(P + (size_t)(r + 8) * kC + col) =
                make_float2(acc[mt][nt][2], acc[mt][nt][3]);
        }
    }
}

// ---------------------------------------------------------------------------
// Reduce split-K partials with symmetric mirroring -> G as bf16 hi/lo.
// ---------------------------------------------------------------------------
__global__ __launch_bounds__(256) void reduce_g(
    const float* __restrict__ part,
    __nv_bfloat16* __restrict__ Gh, __nv_bfloat16* __restrict__ Gl)
{
    const int i = blockIdx.x * 256 + threadIdx.x;
    const int b = i >> 18;
    const int r = (i >> 9) & 511;
    const int c = i & 511;
    const size_t src = ((r >> 7) <= (c >> 7))
        ? ((size_t)r * kC + c) : ((size_t)c * kC + r);
    float sum = 0.f;
#pragma unroll
    for (int s = 0; s < kSplitK; s++)
        sum += part[(size_t)(s * 4 + b) * kC * kC + src];
    const size_t o = (size_t)b * kC * kC + (size_t)r * kC + c;
    __nv_bfloat16 h = __float2bfloat16_rn(sum);
    Gh[o] = h;
    Gl[o] = __float2bfloat16_rn(sum - __bfloat162float(h));
}

// ---------------------------------------------------------------------------
// bf16x3 tensor GEMM (middle GEMMs): C = A @ B^T, CTA 128x128 (4 warps of
// 64x64), K=512, batched over z, BK=16, 3-stage.
// outF -> fp32 out, else out16 -> fp16 single out.
// Stage: Ah|Al|Bh|Bl each 128 rows x 24 bf16 = 6144 B -> 24576 B.
// ---------------------------------------------------------------------------
static constexpr int kYArr   = 128 * 24 * 2;   // 6144 B
static constexpr int kYStage = 4 * kYArr;      // 24576 B
static constexpr int kYSmem  = 3 * kYStage;    // 73728 B

__global__ __launch_bounds__(128, 2) void gemm_tcz(
    const __nv_bfloat16* __restrict__ Ahi, const __nv_bfloat16* __restrict__ Alo,
    size_t strideA,
    const __nv_bfloat16* __restrict__ Bhi, const __nv_bfloat16* __restrict__ Blo,
    size_t strideB,
    float* __restrict__ outF,
    __half* __restrict__ out16,
    int ldc, size_t strideC)
{
    extern __shared__ __align__(16) char smem[];
    const uint32_t sbase = (uint32_t)__cvta_generic_to_shared(smem);

    const int tid = threadIdx.x, wid = tid >> 5, lane = tid & 31;
    const int n0 = blockIdx.x * 128;
    const int m0 = blockIdx.y * 128;
    const int z  = blockIdx.z;
    const int wm = (wid >> 1) * 64, wn = (wid & 1) * 64;

    const __nv_bfloat16* Ah = Ahi + strideA * z + (size_t)m0 * kC;
    const __nv_bfloat16* Al = Alo + strideA * z + (size_t)m0 * kC;
    const __nv_bfloat16* Bh = Bhi + strideB * z + (size_t)n0 * kC;
    const __nv_bfloat16* Bl = Blo + strideB * z + (size_t)n0 * kC;

    const int lr0 = tid >> 1;           // rows lr0, lr0+64
    const int lk8 = (tid & 1) * 8;      // 0 or 8

    auto issue = [&](int kt) {
        const uint32_t stg = sbase + (uint32_t)(kt % 3) * kYStage;
#pragma unroll
        for (int half = 0; half < 2; half++) {
            const int row = lr0 + half * 64;
            const uint32_t d = (uint32_t)(row * 24 + lk8) * 2;
            const size_t ro = (size_t)row * kC + kt * 16 + lk8;
            cp16(stg +             d, Ah + ro);
            cp16(stg +     kYArr + d, Al + ro);
            cp16(stg + 2 * kYArr + d, Bh + ro);
            cp16(stg + 3 * kYArr + d, Bl + ro);
        }
        cp_commit();
    };

    const int aRow = lane & 15;
    const int aKof = (lane >> 4) * 8;
    const int bRow = (lane & 7) + ((lane >> 4) & 1) * 8;
    const int bKof = ((lane >> 3) & 1) * 8;

    float acc[4][8][4];
#pragma unroll
    for (int mt = 0; mt < 4; mt++)
#pragma unroll
        for (int nt = 0; nt < 8; nt++)
#pragma unroll
            for (int i = 0; i < 4; i++) acc[mt][nt][i] = 0.f;

    const int NK = kC / 16;   // 32
    issue(0); issue(1);

#pragma unroll 1
    for (int kt = 0; kt < NK; kt++) {
        cp_wait<1>();
        __syncthreads();
        if (kt + 2 < NK) issue(kt + 2);
        else             cp_commit();

        const uint32_t stg = sbase + (uint32_t)(kt % 3) * kYStage;
        uint32_t ahi[4][4], alo[4][4];
#pragma unroll
        for (int mt = 0; mt < 4; mt++) {
            const uint32_t co = (uint32_t)((wm + mt * 16 + aRow) * 24 + aKof) * 2;
            ldsm_x4(stg +         co, ahi[mt]);
            ldsm_x4(stg + kYArr + co, alo[mt]);
        }
#pragma unroll
        for (int ng = 0; ng < 4; ng++) {
            uint32_t bh[4], bl[4];
            const uint32_t co = (uint32_t)((wn + ng * 16 + bRow) * 24 + bKof) * 2;
            ldsm_x4(stg + 2 * kYArr + co, bh);
            ldsm_x4(stg + 3 * kYArr + co, bl);
#pragma unroll
            for (int mt = 0; mt < 4; mt++) {
#pragma unroll
                for (int j = 0; j < 2; j++) {
                    float* c = acc[mt][ng * 2 + j];
                    mma_bf16(c, ahi[mt], bh[2 * j], bh[2 * j + 1]);
                    mma_bf16(c, ahi[mt], bl[2 * j], bl[2 * j + 1]);
                    mma_bf16(c, alo[mt], bh[2 * j], bh[2 * j + 1]);
                }
            }
        }
    }

    const int g = lane >> 2, tg = lane & 3;
#pragma unroll
    for (int mt = 0; mt < 4; mt++) {
#pragma unroll
        for (int nt = 0; nt < 8; nt++) {
            const int r   = m0 + wm + mt * 16 + g;
            const int col = n0 + wn + nt * 8 + tg * 2;
            const float v0 = acc[mt][nt][0], v1 = acc[mt][nt][1];
            const float v2 = acc[mt][nt][2], v3 = acc[mt][nt][3];
            const size_t o0 = strideC * z + (size_t)r * ldc + col;
            const size_t o1 = strideC * z + (size_t)(r + 8) * ldc + col;
            if (outF) {
                *(float2*)(outF + o0) = make_float2(v0, v1);
                *(float2*)(outF + o1) = make_float2(v2, v3);
            } else {
                *(uint32_t*)(out16 + o0) = pack_h2(v0, v1);
                *(uint32_t*)(out16 + o1) = pack_h2(v2, v3);
            }
        }
    }
}

// ---------------------------------------------------------------------------
// fp16 single x single GEMM (y): C = A @ B^T + bias.
// CTA 128x128 (4 warps of 64x64), K=512, batched over z, BK=16, 3-stage.
// Stage: Ah|Bh each 128 rows x 24 fp16 = 6144 B -> 12288 B.
// ---------------------------------------------------------------------------
static constexpr int kY1Stage = 2 * kYArr;      // 12288 B
static constexpr int kY1Smem  = 3 * kY1Stage;   // 36864 B

__global__ __launch_bounds__(128, 2) void gemm_y16s(
    const __half* __restrict__ A16,
    const __half* __restrict__ B16,
    const float* __restrict__ bias, float* __restrict__ C)
{
    extern __shared__ __align__(16) char smem[];
    const uint32_t sbase = (uint32_t)__cvta_generic_to_shared(smem);

    const int tid = threadIdx.x, wid = tid >> 5, lane = tid & 31;
    const int n0 = blockIdx.x * 128;
    const int m0 = blockIdx.y * 128;
    const int z  = blockIdx.z;
    const int wm = (wid >> 1) * 64, wn = (wid & 1) * 64;

    const __half* Ah = A16 + ((size_t)z * kTok + m0) * kC;
    const __half* Bh = B16 + (size_t)z * kC * kC + (size_t)n0 * kC;

    const int lr0 = tid >> 1;
    const int lk8 = (tid & 1) * 8;

    auto issue = [&](int kt) {
        const uint32_t stg = sbase + (uint32_t)(kt % 3) * kY1Stage;
#pragma unroll
        for (int half = 0; half < 2; half++) {
            const int row = lr0 + half * 64;
            const uint32_t d = (uint32_t)(row * 24 + lk8) * 2;
            const size_t ro = (size_t)row * kC + kt * 16 + lk8;
            cp16(stg +         d, Ah + ro);
            cp16(stg + kYArr + d, Bh + ro);
        }
        cp_commit();
    };

    const int aRow = lane & 15;
    const int aKof = (lane >> 4) * 8;
    const int bRow = (lane & 7) + ((lane >> 4) & 1) * 8;
    const int bKof = ((lane >> 3) & 1) * 8;

    float acc[4][8][4];
#pragma unroll
    for (int mt = 0; mt < 4; mt++)
#pragma unroll
        for (int nt = 0; nt < 8; nt++)
#pragma unroll
            for (int i = 0; i < 4; i++) acc[mt][nt][i] = 0.f;

    const int NK = kC / 16;   // 32
    issue(0); issue(1);

#pragma unroll 1
    for (int kt = 0; kt < NK; kt++) {
        cp_wait<1>();
        __syncthreads();
        if (kt + 2 < NK) issue(kt + 2);
        else             cp_commit();

        const uint32_t stg = sbase + (uint32_t)(kt % 3) * kY1Stage;
        uint32_t ah[4][4];
#pragma unroll
        for (int mt = 0; mt < 4; mt++) {
            const uint32_t co = (uint32_t)((wm + mt * 16 + aRow) * 24 + aKof) * 2;
            ldsm_x4(stg + co, ah[mt]);
        }
#pragma unroll
        for (int ng = 0; ng < 4; ng++) {
            uint32_t bh[4];
            const uint32_t co = (uint32_t)((wn + ng * 16 + bRow) * 24 + bKof) * 2;
            ldsm_x4(stg + kYArr + co, bh);
#pragma unroll
            for (int mt = 0; mt < 4; mt++) {
#pragma unroll
                for (int j = 0; j < 2; j++) {
                    mma_f16(acc[mt][ng * 2 + j], ah[mt],
                            bh[2 * j], bh[2 * j + 1]);
                }
            }
        }
    }

    const int g = lane >> 2, tg = lane & 3;
#pragma unroll
    for (int mt = 0; mt < 4; mt++) {
#pragma unroll
        for (int nt = 0; nt < 8; nt++) {
            const int r   = m0 + wm + mt * 16 + g;
            const int col = n0 + wn + nt * 8 + tg * 2;
            const float b0 = bias[col], b1 = bias[col + 1];
            float* crow = C + ((size_t)z * kTok + r) * kC + col;
            *(float2*)(crow) =
                make_float2(acc[mt][nt][0] + b0, acc[mt][nt][1] + b1);
            *(float2*)(crow + (size_t)8 * kC) =
                make_float2(acc[mt][nt][2] + b0, acc[mt][nt][3] + b1);
        }
    }
}

// ---------------------------------------------------------------------------
// logits_h = SCALE * P1_h @ Wv_h^T (64x64, K=512), row softmax -> attn.
// ---------------------------------------------------------------------------
__global__ __launch_bounds__(256) void logits_softmax(
    const float* __restrict__ P1, const float* __restrict__ Wqkv,
    float* __restrict__ attn)
{
    const int h = blockIdx.x, b = blockIdx.y;
    const float* p1 = P1 + (size_t)b * kC * kC + (size_t)(h * 64) * kC;
    const float* wv = Wqkv + (size_t)(1024 + h * 64) * kC;

    __shared__ float ps[16][68];
    __shared__ float vs[16][68];
    __shared__ float ls[64][68];

    const int tid = threadIdx.x;
    const int ty = tid >> 4, tx = tid & 15;
    const int lr = tid >> 2, lc = (tid & 3) * 4;

    float acc[4][4];
#pragma unroll
    for (int i = 0; i < 4; i++)
#pragma unroll
        for (int j = 0; j < 4; j++) acc[i][j] = 0.f;

    for (int c0 = 0; c0 < kC; c0 += 16) {
        float4 pv = *(const float4*)(p1 + (size_t)lr * kC + c0 + lc);
        float4 vv = *(const float4*)(wv + (size_t)lr * kC + c0 + lc);
        __syncthreads();
        ps[lc+0][lr]=pv.x; ps[lc+1][lr]=pv.y; ps[lc+2][lr]=pv.z; ps[lc+3][lr]=pv.w;
        vs[lc+0][lr]=vv.x; vs[lc+1][lr]=vv.y; vs[lc+2][lr]=vv.z; vs[lc+3][lr]=vv.w;
        __syncthreads();
#pragma unroll
        for (int cc = 0; cc < 16; cc++) {
            float a[4], v[4];
#pragma unroll
            for (int i = 0; i < 4; i++) a[i] = ps[cc][ty * 4 + i];
#pragma unroll
            for (int j = 0; j < 4; j++) v[j] = vs[cc][tx * 4 + j];
#pragma unroll
            for (int i = 0; i < 4; i++)
#pragma unroll
                for (int j = 0; j < 4; j++)
                    acc[i][j] += a[i] * v[j];
        }
    }

    __syncthreads();
#pragma unroll
    for (int i = 0; i < 4; i++)
#pragma unroll
        for (int j = 0; j < 4; j++)
            ls[ty * 4 + i][tx * 4 + j] = acc[i][j];
    __syncthreads();

    const int warp = tid >> 5, lane = tid & 31;
    float* arow_base = attn + (size_t)(b * 8 + h) * 4096;
    for (int r = 0; r < 8; r++) {
        const int d = warp * 8 + r;
        float v1 = kScale * ls[d][lane];
        float v2 = kScale * ls[d][lane + 32];
        float m = fmaxf(v1, v2);
#pragma unroll
        for (int s = 16; s > 0; s >>= 1)
            m = fmaxf(m, __shfl_xor_sync(0xffffffffu, m, s));
        float e1 = expf(v1 - m), e2 = expf(v2 - m);
        float sm = e1 + e2;
#pragma unroll
        for (int s = 16; s > 0; s >>= 1)
            sm += __shfl_xor_sync(0xffffffffu, sm, s);
        float inv = 1.f / sm;
        arow_base[d * 64 + lane]      = e1 * inv;
        arow_base[d * 64 + lane + 32] = e2 * inv;
    }
}

// ---------------------------------------------------------------------------
// Wht_b[c][h*64+d] = sum_e attn_h[d,e] * Wq[h*64+e][c] -> bf16 hi/lo.
// ---------------------------------------------------------------------------
static constexpr int kWhatSmem = (64 * 68 + 64 * 132) * 4;

__device__ __forceinline__ uint32_t pack_hi2b(float a, float b)
{
    __nv_bfloat162 p;
    p.x = __float2bfloat16_rn(a);
    p.y = __float2bfloat16_rn(b);
    return *reinterpret_cast<uint32_t*>(&p);
}
__device__ __forceinline__ uint32_t pack_lo2b(float a, float b, uint32_t hi)
{
    __nv_bfloat162 h = *reinterpret_cast<__nv_bfloat162*>(&hi);
    __nv_bfloat162 p;
    p.x = __float2bfloat16_rn(a - __bfloat162float(h.x));
    p.y = __float2bfloat16_rn(b - __bfloat162float(h.y));
    return *reinterpret_cast<uint32_t*>(&p);
}

__global__ __launch_bounds__(256) void what_t(
    const float* __restrict__ attn, const float* __restrict__ Wqkv,
    __nv_bfloat16* __restrict__ whth, __nv_bfloat16* __restrict__ whtl)
{
    extern __shared__ __align__(16) float ws[];
    float (*at)[68]  = (float(*)[68])ws;
    float (*wq)[132] = (float(*)[132])(ws + 64 * 68);

    const int h = blockIdx.x, b = blockIdx.y;
    const float* ag = attn + (size_t)(b * 8 + h) * 4096;
    const float* Wq = Wqkv + (size_t)(h * 64) * kC;
    const size_t obase = (size_t)b * kC * kC;

    const int tid = threadIdx.x;
    for (int i = tid; i < 4096; i += 256)
        at[i >> 6][i & 63] = ag[i];

    const int dG = (tid & 15) * 4;
    const int cB = tid >> 4;

    for (int cb = 0; cb < 4; cb++) {
        __syncthreads();
        for (int i = 0; i < 8; i++) {
            const int f4 = tid + i * 256;
            const int e  = f4 >> 5;
            const int cq = (f4 & 31) * 4;
            *(float4*)&wq[e][cq] =
                *(const float4*)(Wq + (size_t)e * kC + cb * 128 + cq);
        }
        __syncthreads();

        float o[8][4];
#pragma unroll
        for (int i = 0; i < 8; i++)
#pragma unroll
            for (int j = 0; j < 4; j++) o[i][j] = 0.f;

#pragma unroll 4
        for (int e = 0; e < 64; e++) {
            float a[4], w[8];
#pragma unroll
            for (int j = 0; j < 4; j++) a[j] = at[dG + j][e];
#pragma unroll
            for (int i = 0; i < 8; i++) w[i] = wq[e][cB * 8 + i];
#pragma unroll
            for (int i = 0; i < 8; i++)
#pragma unroll
                for (int j = 0; j < 4; j++)
                    o[i][j] += w[i] * a[j];
        }

#pragma unroll
        for (int i = 0; i < 8; i++) {
            const int c = cb * 128 + cB * 8 + i;
            const size_t oo = obase + (size_t)c * kC + h * 64 + dG;
            uint32_t h0 = pack_hi2b(o[i][0], o[i][1]);
            uint32_t h1 = pack_hi2b(o[i][2], o[i][3]);
            uint32_t l0 = pack_lo2b(o[i][0], o[i][1], h0);
            uint32_t l1 = pack_lo2b(o[i][2], o[i][3], h1);
            ((uint32_t*)(whth + oo))[0] = h0;
            ((uint32_t*)(whth + oo))[1] = h1;
            ((uint32_t*)(whtl + oo))[0] = l0;
            ((uint32_t*)(whtl + oo))[1] = l1;
        }
    }
}

// ---------------------------------------------------------------------------
extern "C" void kernel_launch(void* const* d_in, const int* in_sizes, int n_in,
                              void* d_out, int out_size)
{
    const float* x     = (const float*)d_in[0];
    const float* Wqkv  = (const float*)d_in[1];
    const float* Wproj = (const float*)d_in[2];
    const float* bproj = (const float*)d_in[3];
    float* out = (float*)d_out;

    __half *x16, *wt16;
    __nv_bfloat16 *Gh, *Gl, *whth, *whtl, *wkh, *wkl, *wph, *wpl;
    float *gpart, *P1, *attn;
    cudaGetSymbolAddress((void**)&x16,   g_x16);
    cudaGetSymbolAddress((void**)&gpart, g_gpart);
    cudaGetSymbolAddress((void**)&Gh,    g_Gh);
    cudaGetSymbolAddress((void**)&Gl,    g_Gl);
    cudaGetSymbolAddress((void**)&P1,    g_P1);
    cudaGetSymbolAddress((void**)&attn,  g_attn);
    cudaGetSymbolAddress((void**)&whth,  g_whth);
    cudaGetSymbolAddress((void**)&whtl,  g_whtl);
    cudaGetSymbolAddress((void**)&wt16,  g_wt16);
    cudaGetSymbolAddress((void**)&wkh,   g_wkh);
    cudaGetSymbolAddress((void**)&wkl,   g_wkl);
    cudaGetSymbolAddress((void**)&wph,   g_wph);
    cudaGetSymbolAddress((void**)&wpl,   g_wpl);

    cudaFuncSetAttribute(gemm_gram16,
        cudaFuncAttributeMaxDynamicSharedMemorySize, kGramSmem);
    cudaFuncSetAttribute(what_t,
        cudaFuncAttributeMaxDynamicSharedMemorySize, kWhatSmem);
    cudaFuncSetAttribute(gemm_tcz,
        cudaFuncAttributeMaxDynamicSharedMemorySize, kYSmem);
    cudaFuncSetAttribute(gemm_y16s,
        cudaFuncAttributeMaxDynamicSharedMemorySize, kY1Smem);

    const size_t cc = (size_t)kC * kC;

    // 1) converts/splits: X -> fp16 single; Wk, Wproj -> bf16 hi/lo
    conv_f16<<<(kM * kC / 4 + 255) / 256, 256>>>(x, x16, kM * kC / 4);
    split_f32<<<((int)cc / 4 + 255) / 256, 256>>>(Wqkv + cc, wkh, wkl, (int)cc / 4);
    split_f32<<<((int)cc / 4 + 255) / 256, 256>>>(Wproj, wph, wpl, (int)cc / 4);

    // 2) Gram partials (fp16 single, split-K 8)
    gemm_gram16<<<dim3(10, 4 * kSplitK), 128, kGramSmem>>>(x16, gpart);

    // 3) reduce + mirror -> G (bf16 hi/lo)
    reduce_g<<<(4 * (int)cc) / 256, 256>>>(gpart, Gh, Gl);

    // 4) P1_b = Wk @ G_b  (G symmetric)  [bf16x3, fp32 out]
    gemm_tcz<<<dim3(4, 4, 4), 128, kYSmem>>>(
        wkh, wkl, 0, Gh, Gl, cc, P1, nullptr, kC, cc);

    // 5) logits + softmax -> attn
    logits_softmax<<<dim3(8, 4), 256>>>(P1, Wqkv, attn);

    // 6) Wht_b = (attn_h @ Wq_h)^T  -> bf16 hi/lo
    what_t<<<dim3(8, 4), 256, kWhatSmem>>>(attn, Wqkv, whth, whtl);

    // 7) Wt_b = Wproj @ Wht_b^T  [bf16x3, fp16 single out]
    gemm_tcz<<<dim3(4, 4, 4), 128, kYSmem>>>(
        wph, wpl, 0, whth, whtl, cc, nullptr, wt16, kC, cc);

    // 8) y = X @ Wt_b^T + bproj  [fp16 single x single]
    gemm_y16s<<<dim3(4, kTok / 128, 4), 128, kY1Smem>>>(
        x16, wt16, bproj, out);
}

// round 17
// speedup vs baseline: 1.7550x; 1.0718x over previous
#include <cuda_runtime.h>
#include <cuda_bf16.h>
#include <cuda_fp16.h>
#include <cstdint>
#include <cstddef>

// ---------------------------------------------------------------------------
// ChannelAttention via Gram factorization.
//   G_b   = X_b^T X_b          (fp16 single x single mma; split-K 8; 4-stage)
//   P1_b  = Wk @ G_b           (bf16x3 mma)
//   logit = softmax(SCALE * P1_h @ Wv_h^T)   (FFMA, tiny)
//   Wht_b = (attn_h @ Wq_h)^T                (FFMA, tiny, emits fp16)
//   Wt_b  = Wproj @ Wht_b^T                  (fp16 single mma, fp16 out)
//   y     = X @ Wt_b^T + bproj               (fp16 single mma; 4-stage)
// Round 17: step 7 drops bf16x3 -> fp16 single (unamplified error, -18us);
// gram & y pipelines deepened to 4 stages (prefetch distance 3).
// ---------------------------------------------------------------------------

static constexpr int   kTok   = 8192;
static constexpr int   kC     = 512;
static constexpr int   kM     = 4 * kTok;       // 32768
static constexpr float kScale = 0.125f;
static constexpr int   kSplitK = 8;             // gram split-K
static constexpr int   kKS     = kTok / kSplitK;  // 1024 tokens per split

// Scratch (device globals; all read locations rewritten each launch)
__device__ __half g_x16 [(size_t)kM * kC];
__device__ float g_gpart[(size_t)kSplitK * 4 * kC * kC];
__device__ __nv_bfloat16 g_Gh [(size_t)4 * kC * kC];
__device__ __nv_bfloat16 g_Gl [(size_t)4 * kC * kC];
__device__ float g_P1   [(size_t)4 * kC * kC];
__device__ float g_attn [(size_t)32 * 64 * 64];
__device__ __half g_wht16[(size_t)4 * kC * kC];
__device__ __half g_wt16 [(size_t)4 * kC * kC];
__device__ __nv_bfloat16 g_wkh[(size_t)kC * kC];
__device__ __nv_bfloat16 g_wkl[(size_t)kC * kC];
__device__ __half g_wp16[(size_t)kC * kC];

// ---------------------------------------------------------------------------
// primitives
// ---------------------------------------------------------------------------
__device__ __forceinline__ void ldsm_x4(uint32_t addr, uint32_t* r)
{
    asm volatile("ldmatrix.sync.aligned.m8n8.x4.shared.b16 {%0,%1,%2,%3}, [%4];\n"
                 : "=r"(r[0]), "=r"(r[1]), "=r"(r[2]), "=r"(r[3]) : "r"(addr));
}
__device__ __forceinline__ void ldsm_x4_t(uint32_t addr, uint32_t* r)
{
    asm volatile("ldmatrix.sync.aligned.m8n8.x4.trans.shared.b16 {%0,%1,%2,%3}, [%4];\n"
                 : "=r"(r[0]), "=r"(r[1]), "=r"(r[2]), "=r"(r[3]) : "r"(addr));
}
__device__ __forceinline__ void mma_bf16(float* c, const uint32_t* a,
                                         uint32_t b0, uint32_t b1)
{
    asm volatile(
        "mma.sync.aligned.m16n8k16.row.col.f32.bf16.bf16.f32 "
        "{%0,%1,%2,%3}, {%4,%5,%6,%7}, {%8,%9}, {%0,%1,%2,%3};\n"
        : "+f"(c[0]), "+f"(c[1]), "+f"(c[2]), "+f"(c[3])
        : "r"(a[0]), "r"(a[1]), "r"(a[2]), "r"(a[3]), "r"(b0), "r"(b1));
}
__device__ __forceinline__ void mma_f16(float* c, const uint32_t* a,
                                        uint32_t b0, uint32_t b1)
{
    asm volatile(
        "mma.sync.aligned.m16n8k16.row.col.f32.f16.f16.f32 "
        "{%0,%1,%2,%3}, {%4,%5,%6,%7}, {%8,%9}, {%0,%1,%2,%3};\n"
        : "+f"(c[0]), "+f"(c[1]), "+f"(c[2]), "+f"(c[3])
        : "r"(a[0]), "r"(a[1]), "r"(a[2]), "r"(a[3]), "r"(b0), "r"(b1));
}
__device__ __forceinline__ void cp16(uint32_t dst, const void* src)
{
    asm volatile("cp.async.cg.shared.global [%0], [%1], 16;\n" :: "r"(dst), "l"(src));
}
__device__ __forceinline__ void cp_commit()
{
    asm volatile("cp.async.commit_group;\n");
}
template <int N> __device__ __forceinline__ void cp_wait()
{
    asm volatile("cp.async.wait_group %0;\n" :: "n"(N));
}
__device__ __forceinline__ uint32_t pack_h2(float a, float b)
{
    __half2 p;
    p.x = __float2half_rn(a);
    p.y = __float2half_rn(b);
    return *reinterpret_cast<uint32_t*>(&p);
}

// ---------------------------------------------------------------------------
// fp32 -> (hi, lo) bf16 split
// ---------------------------------------------------------------------------
__global__ __launch_bounds__(256) void split_f32(
    const float* __restrict__ src,
    __nv_bfloat16* __restrict__ hi, __nv_bfloat16* __restrict__ lo, int n4)
{
    int i = blockIdx.x * blockDim.x + threadIdx.x;
    if (i >= n4) return;
    float4 f = ((const float4*)src)[i];
    float a[4] = {f.x, f.y, f.z, f.w};
    __nv_bfloat16 h[4], l[4];
#pragma unroll
    for (int j = 0; j < 4; j++) {
        h[j] = __float2bfloat16_rn(a[j]);
        l[j] = __float2bfloat16_rn(a[j] - __bfloat162float(h[j]));
    }
    ((uint2*)hi)[i] = *(uint2*)h;
    ((uint2*)lo)[i] = *(uint2*)l;
}

// fp32 -> fp16 convert (single)
__global__ __launch_bounds__(256) void conv_f16(
    const float* __restrict__ src, __half* __restrict__ dst, int n4)
{
    int i = blockIdx.x * blockDim.x + threadIdx.x;
    if (i >= n4) return;
    float4 f = ((const float4*)src)[i];
    __half h[4];
    h[0] = __float2half_rn(f.x);
    h[1] = __float2half_rn(f.y);
    h[2] = __float2half_rn(f.z);
    h[3] = __float2half_rn(f.w);
    ((uint2*)dst)[i] = *(uint2*)h;
}

// ---------------------------------------------------------------------------
// Gram partials (fp16 single x single), split-K 8, BK=16, 4-stage.
// 128 threads, 4 warps of 64x64, CTA 128x128 upper-tri pairs.
// Stage: A | B, each 16 rows x 136 fp16 = 4352 B -> 8704 B.
// ---------------------------------------------------------------------------
static constexpr int kGArr      = 16 * 136 * 2;       // 4352 B
static constexpr int kGramStage = 2 * kGArr;          // 8704 B
static constexpr int kGramSmem  = 4 * kGramStage;     // 34816 B

__global__ __launch_bounds__(128, 2) void gemm_gram16(
    const __half* __restrict__ X16,
    float* __restrict__ part)
{
    extern __shared__ __align__(16) char smem[];
    const uint32_t sbase = (uint32_t)__cvta_generic_to_shared(smem);

    int p = blockIdx.x, mb = 0;
    while (p >= 4 - mb) { p -= 4 - mb; mb++; }
    const int m0 = mb * 128, n0 = (mb + p) * 128;
    const int bz = blockIdx.y;           // b*kSplitK + s
    const int b = bz >> 3, s = bz & 7;
    const size_t tokBase = (size_t)b * kTok + (size_t)s * kKS;

    const int tid = threadIdx.x, wid = tid >> 5, lane = tid & 31;
    const int wm = (wid >> 1) * 64, wn = (wid & 1) * 64;

    const int lr0 = tid >> 3;              // row 0..15
    const int ch0 = (tid & 7) * 16;        // chunk cols ch0, ch0+8

    auto issue = [&](int kt) {
        const uint32_t stg = sbase + (uint32_t)(kt & 3) * kGramStage;
        const size_t ro = (tokBase + (size_t)kt * 16 + lr0) * kC;
#pragma unroll
        for (int cg = 0; cg < 2; cg++) {
            const int ch = ch0 + cg * 8;
            const uint32_t d = (uint32_t)(lr0 * 136 + ch) * 2;
            cp16(stg +         d, X16 + ro + m0 + ch);
            cp16(stg + kGArr + d, X16 + ro + n0 + ch);
        }
        cp_commit();
    };

    // trans fragment lane mapping
    const int kA = (lane & 7) + ((lane >> 4) & 1) * 8;
    const int mA = ((lane >> 3) & 1) * 8;
    const int kB = (lane & 7) + ((lane >> 3) & 1) * 8;
    const int nB = ((lane >> 4) & 1) * 8;

    float acc[4][8][4];
#pragma unroll
    for (int mt = 0; mt < 4; mt++)
#pragma unroll
        for (int nt = 0; nt < 8; nt++)
#pragma unroll
            for (int i = 0; i < 4; i++) acc[mt][nt][i] = 0.f;

    const int NK = kKS / 16;   // 64
    issue(0); issue(1); issue(2);

#pragma unroll 1
    for (int kt = 0; kt < NK; kt++) {
        cp_wait<2>();
        __syncthreads();
        if (kt + 3 < NK) issue(kt + 3);
        else             cp_commit();

        const uint32_t stg = sbase + (uint32_t)(kt & 3) * kGramStage;
        uint32_t ah[4][4];
#pragma unroll
        for (int mt = 0; mt < 4; mt++) {
            const uint32_t co = (uint32_t)(kA * 136 + wm + mt * 16 + mA) * 2;
            ldsm_x4_t(stg + co, ah[mt]);
        }
#pragma unroll
        for (int ng = 0; ng < 4; ng++) {
            uint32_t bh[4];
            const uint32_t co = (uint32_t)(kB * 136 + wn + ng * 16 + nB) * 2;
            ldsm_x4_t(stg + kGArr + co, bh);
#pragma unroll
            for (int mt = 0; mt < 4; mt++) {
#pragma unroll
                for (int j = 0; j < 2; j++) {
                    mma_f16(acc[mt][ng * 2 + j], ah[mt],
                            bh[2 * j], bh[2 * j + 1]);
                }
            }
        }
    }

    const int g = lane >> 2, tg = lane & 3;
    float* P = part + (size_t)(s * 4 + b) * kC * kC;
#pragma unroll
    for (int mt = 0; mt < 4; mt++) {
#pragma unroll
        for (int nt = 0; nt < 8; nt++) {
            const int r   = m0 + wm + mt * 16 + g;
            const int col = n0 + wn + nt * 8 + tg * 2;
            *(float2*)(P + (size_t)r * kC + col) =
                make_float2(acc[mt][nt][0], acc[mt][nt][1]);
            *(float2*)(P + (size_t)(r + 8) * kC + col) =
                make_float2(acc[mt][nt][2], acc[mt][nt][3]);
        }
    }
}

// ---------------------------------------------------------------------------
// Reduce split-K partials with symmetric mirroring -> G as bf16 hi/lo.
// ---------------------------------------------------------------------------
__global__ __launch_bounds__(256) void reduce_g(
    const float* __restrict__ part,
    __nv_bfloat16* __restrict__ Gh, __nv_bfloat16* __restrict__ Gl)
{
    const int i = blockIdx.x * 256 + threadIdx.x;
    const int b = i >> 18;
    const int r = (i >> 9) & 511;
    const int c = i & 511;
    const size_t src = ((r >> 7) <= (c >> 7))
        ? ((size_t)r * kC + c) : ((size_t)c * kC + r);
    float sum = 0.f;
#pragma unroll
    for (int s = 0; s < kSplitK; s++)
        sum += part[(size_t)(s * 4 + b) * kC * kC + src];
    const size_t o = (size_t)b * kC * kC + (size_t)r * kC + c;
    __nv_bfloat16 h = __float2bfloat16_rn(sum);
    Gh[o] = h;
    Gl[o] = __float2bfloat16_rn(sum - __bfloat162float(h));
}

// ---------------------------------------------------------------------------
// bf16x3 tensor GEMM (step 4 only): C = A @ B^T, CTA 128x128 (4 warps of
// 64x64), K=512, batched over z, BK=16, 3-stage, fp32 out.
// Stage: Ah|Al|Bh|Bl each 128 rows x 24 bf16 = 6144 B -> 24576 B.
// ---------------------------------------------------------------------------
static constexpr int kYArr   = 128 * 24 * 2;   // 6144 B
static constexpr int kYStage = 4 * kYArr;      // 24576 B
static constexpr int kYSmem  = 3 * kYStage;    // 73728 B

__global__ __launch_bounds__(128, 2) void gemm_tcz(
    const __nv_bfloat16* __restrict__ Ahi, const __nv_bfloat16* __restrict__ Alo,
    size_t strideA,
    const __nv_bfloat16* __restrict__ Bhi, const __nv_bfloat16* __restrict__ Blo,
    size_t strideB,
    float* __restrict__ outF,
    int ldc, size_t strideC)
{
    extern __shared__ __align__(16) char smem[];
    const uint32_t sbase = (uint32_t)__cvta_generic_to_shared(smem);

    const int tid = threadIdx.x, wid = tid >> 5, lane = tid & 31;
    const int n0 = blockIdx.x * 128;
    const int m0 = blockIdx.y * 128;
    const int z  = blockIdx.z;
    const int wm = (wid >> 1) * 64, wn = (wid & 1) * 64;

    const __nv_bfloat16* Ah = Ahi + strideA * z + (size_t)m0 * kC;
    const __nv_bfloat16* Al = Alo + strideA * z + (size_t)m0 * kC;
    const __nv_bfloat16* Bh = Bhi + strideB * z + (size_t)n0 * kC;
    const __nv_bfloat16* Bl = Blo + strideB * z + (size_t)n0 * kC;

    const int lr0 = tid >> 1;           // rows lr0, lr0+64
    const int lk8 = (tid & 1) * 8;      // 0 or 8

    auto issue = [&](int kt) {
        const uint32_t stg = sbase + (uint32_t)(kt % 3) * kYStage;
#pragma unroll
        for (int half = 0; half < 2; half++) {
            const int row = lr0 + half * 64;
            const uint32_t d = (uint32_t)(row * 24 + lk8) * 2;
            const size_t ro = (size_t)row * kC + kt * 16 + lk8;
            cp16(stg +             d, Ah + ro);
            cp16(stg +     kYArr + d, Al + ro);
            cp16(stg + 2 * kYArr + d, Bh + ro);
            cp16(stg + 3 * kYArr + d, Bl + ro);
        }
        cp_commit();
    };

    const int aRow = lane & 15;
    const int aKof = (lane >> 4) * 8;
    const int bRow = (lane & 7) + ((lane >> 4) & 1) * 8;
    const int bKof = ((lane >> 3) & 1) * 8;

    float acc[4][8][4];
#pragma unroll
    for (int mt = 0; mt < 4; mt++)
#pragma unroll
        for (int nt = 0; nt < 8; nt++)
#pragma unroll
            for (int i = 0; i < 4; i++) acc[mt][nt][i] = 0.f;

    const int NK = kC / 16;   // 32
    issue(0); issue(1);

#pragma unroll 1
    for (int kt = 0; kt < NK; kt++) {
        cp_wait<1>();
        __syncthreads();
        if (kt + 2 < NK) issue(kt + 2);
        else             cp_commit();

        const uint32_t stg = sbase + (uint32_t)(kt % 3) * kYStage;
        uint32_t ahi[4][4], alo[4][4];
#pragma unroll
        for (int mt = 0; mt < 4; mt++) {
            const uint32_t co = (uint32_t)((wm + mt * 16 + aRow) * 24 + aKof) * 2;
            ldsm_x4(stg +         co, ahi[mt]);
            ldsm_x4(stg + kYArr + co, alo[mt]);
        }
#pragma unroll
        for (int ng = 0; ng < 4; ng++) {
            uint32_t bh[4], bl[4];
            const uint32_t co = (uint32_t)((wn + ng * 16 + bRow) * 24 + bKof) * 2;
            ldsm_x4(stg + 2 * kYArr + co, bh);
            ldsm_x4(stg + 3 * kYArr + co, bl);
#pragma unroll
            for (int mt = 0; mt < 4; mt++) {
#pragma unroll
                for (int j = 0; j < 2; j++) {
                    float* c = acc[mt][ng * 2 + j];
                    mma_bf16(c, ahi[mt], bh[2 * j], bh[2 * j + 1]);
                    mma_bf16(c, ahi[mt], bl[2 * j], bl[2 * j + 1]);
                    mma_bf16(c, alo[mt], bh[2 * j], bh[2 * j + 1]);
                }
            }
        }
    }

    const int g = lane >> 2, tg = lane & 3;
#pragma unroll
    for (int mt = 0; mt < 4; mt++) {
#pragma unroll
        for (int nt = 0; nt < 8; nt++) {
            const int r   = m0 + wm + mt * 16 + g;
            const int col = n0 + wn + nt * 8 + tg * 2;
            const size_t o0 = strideC * z + (size_t)r * ldc + col;
            const size_t o1 = strideC * z + (size_t)(r + 8) * ldc + col;
            *(float2*)(outF + o0) = make_float2(acc[mt][nt][0], acc[mt][nt][1]);
            *(float2*)(outF + o1) = make_float2(acc[mt][nt][2], acc[mt][nt][3]);
        }
    }
}

// ---------------------------------------------------------------------------
// fp16 single x single GEMM (steps 7 & 8): C = A @ B^T (+bias).
// CTA 128x128 (4 warps of 64x64), K=512, batched over z, BK=16, 4-stage.
// outF -> fp32 out (+bias); else out16 -> fp16 out.
// Stage: A|B each 128 rows x 24 fp16 = 6144 B -> 12288 B.
// ---------------------------------------------------------------------------
static constexpr int kY1Stage = 2 * kYArr;      // 12288 B
static constexpr int kY1Smem  = 4 * kY1Stage;   // 49152 B

__global__ __launch_bounds__(128, 2) void gemm_f16z(
    const __half* __restrict__ A16, size_t strideA,
    const __half* __restrict__ B16, size_t strideB,
    const float* __restrict__ bias,
    float* __restrict__ outF, __half* __restrict__ out16,
    int ldc, size_t strideC)
{
    extern __shared__ __align__(16) char smem[];
    const uint32_t sbase = (uint32_t)__cvta_generic_to_shared(smem);

    const int tid = threadIdx.x, wid = tid >> 5, lane = tid & 31;
    const int n0 = blockIdx.x * 128;
    const int m0 = blockIdx.y * 128;
    const int z  = blockIdx.z;
    const int wm = (wid >> 1) * 64, wn = (wid & 1) * 64;

    const __half* Ah = A16 + strideA * z + (size_t)m0 * kC;
    const __half* Bh = B16 + strideB * z + (size_t)n0 * kC;

    const int lr0 = tid >> 1;
    const int lk8 = (tid & 1) * 8;

    auto issue = [&](int kt) {
        const uint32_t stg = sbase + (uint32_t)(kt & 3) * kY1Stage;
#pragma unroll
        for (int half = 0; half < 2; half++) {
            const int row = lr0 + half * 64;
            const uint32_t d = (uint32_t)(row * 24 + lk8) * 2;
            const size_t ro = (size_t)row * kC + kt * 16 + lk8;
            cp16(stg +         d, Ah + ro);
            cp16(stg + kYArr + d, Bh + ro);
        }
        cp_commit();
    };

    const int aRow = lane & 15;
    const int aKof = (lane >> 4) * 8;
    const int bRow = (lane & 7) + ((lane >> 4) & 1) * 8;
    const int bKof = ((lane >> 3) & 1) * 8;

    float acc[4][8][4];
#pragma unroll
    for (int mt = 0; mt < 4; mt++)
#pragma unroll
        for (int nt = 0; nt < 8; nt++)
#pragma unroll
            for (int i = 0; i < 4; i++) acc[mt][nt][i] = 0.f;

    const int NK = kC / 16;   // 32
    issue(0); issue(1); issue(2);

#pragma unroll 1
    for (int kt = 0; kt < NK; kt++) {
        cp_wait<2>();
        __syncthreads();
        if (kt + 3 < NK) issue(kt + 3);
        else             cp_commit();

        const uint32_t stg = sbase + (uint32_t)(kt & 3) * kY1Stage;
        uint32_t ah[4][4];
#pragma unroll
        for (int mt = 0; mt < 4; mt++) {
            const uint32_t co = (uint32_t)((wm + mt * 16 + aRow) * 24 + aKof) * 2;
            ldsm_x4(stg + co, ah[mt]);
        }
#pragma unroll
        for (int ng = 0; ng < 4; ng++) {
            uint32_t bh[4];
            const uint32_t co = (uint32_t)((wn + ng * 16 + bRow) * 24 + bKof) * 2;
            ldsm_x4(stg + kYArr + co, bh);
#pragma unroll
            for (int mt = 0; mt < 4; mt++) {
#pragma unroll
                for (int j = 0; j < 2; j++) {
                    mma_f16(acc[mt][ng * 2 + j], ah[mt],
                            bh[2 * j], bh[2 * j + 1]);
                }
            }
        }
    }

    const int g = lane >> 2, tg = lane & 3;
#pragma unroll
    for (int mt = 0; mt < 4; mt++) {
#pragma unroll
        for (int nt = 0; nt < 8; nt++) {
            const int r   = m0 + wm + mt * 16 + g;
            const int col = n0 + wn + nt * 8 + tg * 2;
            float v0 = acc[mt][nt][0], v1 = acc[mt][nt][1];
            float v2 = acc[mt][nt][2], v3 = acc[mt][nt][3];
            if (bias) {
                v0 += bias[col]; v1 += bias[col + 1];
                v2 += bias[col]; v3 += bias[col + 1];
            }
            const size_t o0 = strideC * z + (size_t)r * ldc + col;
            const size_t o1 = strideC * z + (size_t)(r + 8) * ldc + col;
            if (outF) {
                *(float2*)(outF + o0) = make_float2(v0, v1);
                *(float2*)(outF + o1) = make_float2(v2, v3);
            } else {
                *(uint32_t*)(out16 + o0) = pack_h2(v0, v1);
                *(uint32_t*)(out16 + o1) = pack_h2(v2, v3);
            }
        }
    }
}

// ---------------------------------------------------------------------------
// logits_h = SCALE * P1_h @ Wv_h^T (64x64, K=512), row softmax -> attn.
// ---------------------------------------------------------------------------
__global__ __launch_bounds__(256) void logits_softmax(
    const float* __restrict__ P1, const float* __restrict__ Wqkv,
    float* __restrict__ attn)
{
    const int h = blockIdx.x, b = blockIdx.y;
    const float* p1 = P1 + (size_t)b * kC * kC + (size_t)(h * 64) * kC;
    const float* wv = Wqkv + (size_t)(1024 + h * 64) * kC;

    __shared__ float ps[16][68];
    __shared__ float vs[16][68];
    __shared__ float ls[64][68];

    const int tid = threadIdx.x;
    const int ty = tid >> 4, tx = tid & 15;
    const int lr = tid >> 2, lc = (tid & 3) * 4;

    float acc[4][4];
#pragma unroll
    for (int i = 0; i < 4; i++)
#pragma unroll
        for (int j = 0; j < 4; j++) acc[i][j] = 0.f;

    for (int c0 = 0; c0 < kC; c0 += 16) {
        float4 pv = *(const float4*)(p1 + (size_t)lr * kC + c0 + lc);
        float4 vv = *(const float4*)(wv + (size_t)lr * kC + c0 + lc);
        __syncthreads();
        ps[lc+0][lr]=pv.x; ps[lc+1][lr]=pv.y; ps[lc+2][lr]=pv.z; ps[lc+3][lr]=pv.w;
        vs[lc+0][lr]=vv.x; vs[lc+1][lr]=vv.y; vs[lc+2][lr]=vv.z; vs[lc+3][lr]=vv.w;
        __syncthreads();
#pragma unroll
        for (int cc = 0; cc < 16; cc++) {
            float a[4], v[4];
#pragma unroll
            for (int i = 0; i < 4; i++) a[i] = ps[cc][ty * 4 + i];
#pragma unroll
            for (int j = 0; j < 4; j++) v[j] = vs[cc][tx * 4 + j];
#pragma unroll
            for (int i = 0; i < 4; i++)
#pragma unroll
                for (int j = 0; j < 4; j++)
                    acc[i][j] += a[i] * v[j];
        }
    }

    __syncthreads();
#pragma unroll
    for (int i = 0; i < 4; i++)
#pragma unroll
        for (int j = 0; j < 4; j++)
            ls[ty * 4 + i][tx * 4 + j] = acc[i][j];
    __syncthreads();

    const int warp = tid >> 5, lane = tid & 31;
    float* arow_base = attn + (size_t)(b * 8 + h) * 4096;
    for (int r = 0; r < 8; r++) {
        const int d = warp * 8 + r;
        float v1 = kScale * ls[d][lane];
        float v2 = kScale * ls[d][lane + 32];
        float m = fmaxf(v1, v2);
#pragma unroll
        for (int s = 16; s > 0; s >>= 1)
            m = fmaxf(m, __shfl_xor_sync(0xffffffffu, m, s));
        float e1 = expf(v1 - m), e2 = expf(v2 - m);
        float sm = e1 + e2;
#pragma unroll
        for (int s = 16; s > 0; s >>= 1)
            sm += __shfl_xor_sync(0xffffffffu, sm, s);
        float inv = 1.f / sm;
        arow_base[d * 64 + lane]      = e1 * inv;
        arow_base[d * 64 + lane + 32] = e2 * inv;
    }
}

// ---------------------------------------------------------------------------
// Wht_b[c][h*64+d] = sum_e attn_h[d,e] * Wq[h*64+e][c] -> fp16 single.
// ---------------------------------------------------------------------------
static constexpr int kWhatSmem = (64 * 68 + 64 * 132) * 4;

__global__ __launch_bounds__(256) void what_t(
    const float* __restrict__ attn, const float* __restrict__ Wqkv,
    __half* __restrict__ wht16)
{
    extern __shared__ __align__(16) float ws[];
    float (*at)[68]  = (float(*)[68])ws;
    float (*wq)[132] = (float(*)[132])(ws + 64 * 68);

    const int h = blockIdx.x, b = blockIdx.y;
    const float* ag = attn + (size_t)(b * 8 + h) * 4096;
    const float* Wq = Wqkv + (size_t)(h * 64) * kC;
    const size_t obase = (size_t)b * kC * kC;

    const int tid = threadIdx.x;
    for (int i = tid; i < 4096; i += 256)
        at[i >> 6][i & 63] = ag[i];

    const int dG = (tid & 15) * 4;
    const int cB = tid >> 4;

    for (int cb = 0; cb < 4; cb++) {
        __syncthreads();
        for (int i = 0; i < 8; i++) {
            const int f4 = tid + i * 256;
            const int e  = f4 >> 5;
            const int cq = (f4 & 31) * 4;
            *(float4*)&wq[e][cq] =
                *(const float4*)(Wq + (size_t)e * kC + cb * 128 + cq);
        }
        __syncthreads();

        float o[8][4];
#pragma unroll
        for (int i = 0; i < 8; i++)
#pragma unroll
            for (int j = 0; j < 4; j++) o[i][j] = 0.f;

#pragma unroll 4
        for (int e = 0; e < 64; e++) {
            float a[4], w[8];
#pragma unroll
            for (int j = 0; j < 4; j++) a[j] = at[dG + j][e];
#pragma unroll
            for (int i = 0; i < 8; i++) w[i] = wq[e][cB * 8 + i];
#pragma unroll
            for (int i = 0; i < 8; i++)
#pragma unroll
                for (int j = 0; j < 4; j++)
                    o[i][j] += w[i] * a[j];
        }

#pragma unroll
        for (int i = 0; i < 8; i++) {
            const int c = cb * 128 + cB * 8 + i;
            const size_t oo = obase + (size_t)c * kC + h * 64 + dG;
            ((uint32_t*)(wht16 + oo))[0] = pack_h2(o[i][0], o[i][1]);
            ((uint32_t*)(wht16 + oo))[1] = pack_h2(o[i][2], o[i][3]);
        }
    }
}

// ---------------------------------------------------------------------------
extern "C" void kernel_launch(void* const* d_in, const int* in_sizes, int n_in,
                              void* d_out, int out_size)
{
    const float* x     = (const float*)d_in[0];
    const float* Wqkv  = (const float*)d_in[1];
    const float* Wproj = (const float*)d_in[2];
    const float* bproj = (const float*)d_in[3];
    float* out = (float*)d_out;

    __half *x16, *wht16, *wt16, *wp16;
    __nv_bfloat16 *Gh, *Gl, *wkh, *wkl;
    float *gpart, *P1, *attn;
    cudaGetSymbolAddress((void**)&x16,   g_x16);
    cudaGetSymbolAddress((void**)&gpart, g_gpart);
    cudaGetSymbolAddress((void**)&Gh,    g_Gh);
    cudaGetSymbolAddress((void**)&Gl,    g_Gl);
    cudaGetSymbolAddress((void**)&P1,    g_P1);
    cudaGetSymbolAddress((void**)&attn,  g_attn);
    cudaGetSymbolAddress((void**)&wht16, g_wht16);
    cudaGetSymbolAddress((void**)&wt16,  g_wt16);
    cudaGetSymbolAddress((void**)&wkh,   g_wkh);
    cudaGetSymbolAddress((void**)&wkl,   g_wkl);
    cudaGetSymbolAddress((void**)&wp16,  g_wp16);

    cudaFuncSetAttribute(gemm_gram16,
        cudaFuncAttributeMaxDynamicSharedMemorySize, kGramSmem);
    cudaFuncSetAttribute(what_t,
        cudaFuncAttributeMaxDynamicSharedMemorySize, kWhatSmem);
    cudaFuncSetAttribute(gemm_tcz,
        cudaFuncAttributeMaxDynamicSharedMemorySize, kYSmem);
    cudaFuncSetAttribute(gemm_f16z,
        cudaFuncAttributeMaxDynamicSharedMemorySize, kY1Smem);

    const size_t cc = (size_t)kC * kC;

    // 1) converts/splits: X, Wproj -> fp16 single; Wk -> bf16 hi/lo
    conv_f16<<<(kM * kC / 4 + 255) / 256, 256>>>(x, x16, kM * kC / 4);
    split_f32<<<((int)cc / 4 + 255) / 256, 256>>>(Wqkv + cc, wkh, wkl, (int)cc / 4);
    conv_f16<<<((int)cc / 4 + 255) / 256, 256>>>(Wproj, wp16, (int)cc / 4);

    // 2) Gram partials (fp16 single, split-K 8, 4-stage)
    gemm_gram16<<<dim3(10, 4 * kSplitK), 128, kGramSmem>>>(x16, gpart);

    // 3) reduce + mirror -> G (bf16 hi/lo)
    reduce_g<<<(4 * (int)cc) / 256, 256>>>(gpart, Gh, Gl);

    // 4) P1_b = Wk @ G_b  (G symmetric)  [bf16x3, fp32 out]
    gemm_tcz<<<dim3(4, 4, 4), 128, kYSmem>>>(
        wkh, wkl, 0, Gh, Gl, cc, P1, kC, cc);

    // 5) logits + softmax -> attn
    logits_softmax<<<dim3(8, 4), 256>>>(P1, Wqkv, attn);

    // 6) Wht_b = (attn_h @ Wq_h)^T  -> fp16 single
    what_t<<<dim3(8, 4), 256, kWhatSmem>>>(attn, Wqkv, wht16);

    // 7) Wt_b = Wproj @ Wht_b^T  [fp16 single, fp16 out]
    gemm_f16z<<<dim3(4, 4, 4), 128, kY1Smem>>>(
        wp16, 0, wht16, cc, nullptr, nullptr, wt16, kC, cc);

    // 8) y = X @ Wt_b^T + bproj  [fp16 single, fp32 out]
    gemm_f16z<<<dim3(4, kTok / 128, 4), 128, kY1Smem>>>(
        x16, (size_t)kTok * kC, wt16, cc, bproj, out, nullptr,
        kC, (size_t)kTok * kC);
}